// round 1
// baseline (speedup 1.0000x reference)
#include <cuda_runtime.h>
#include <math.h>

#define MROWS 16384   // B*T = 8*2048
#define CDIM  1024
#define HNUM  16
#define DDIM  64
#define TSEQ  2048
#define BSZ   8

// ---------------- scratch (static device memory; no runtime allocation) ----------------
__device__ float g_t1 [(size_t)MROWS * 160];
__device__ float g_xdd[5][(size_t)MROWS * CDIM];
__device__ float g_h1 [(size_t)MROWS * 64];
__device__ float g_w  [(size_t)MROWS * CDIM];
__device__ float g_kb [(size_t)MROWS * CDIM];
__device__ float g_vb [(size_t)MROWS * CDIM];
__device__ float g_rb [(size_t)MROWS * CDIM];
__device__ float g_gb [(size_t)MROWS * CDIM];
__device__ float g_yb [(size_t)MROWS * CDIM];
__device__ float g_g1 [(size_t)MROWS * 160];

// ======================================================================================
// GEMM, B-transposed layout:  C[m,n] = sum_k A[m,k] * B[n,k]
// A: MxK row-major, B: NxK row-major. M,N multiples of 128, K multiple of 8.
// EPI: 0 = plain store, 1 = c *= exp(min(w[m,n],0))
// ======================================================================================
template <int EPI>
__global__ void __launch_bounds__(256) sgemm_bt(
    const float* __restrict__ A, const float* __restrict__ B, float* __restrict__ C,
    int M, int N, int K, const float* __restrict__ wptr)
{
    __shared__ float As[8][132];
    __shared__ float Bs[8][132];
    const int tid = threadIdx.x;
    const int bm = blockIdx.y, bn = blockIdx.x;
    const int lr = tid >> 1;           // 0..127
    const int lc = (tid & 1) << 2;     // 0 or 4
    const float* Ap = A + ((size_t)(bm * 128 + lr)) * K + lc;
    const float* Bp = B + ((size_t)(bn * 128 + lr)) * K + lc;
    const int tx = tid & 15, ty = tid >> 4;

    float acc[8][8];
#pragma unroll
    for (int i = 0; i < 8; i++)
#pragma unroll
        for (int j = 0; j < 8; j++) acc[i][j] = 0.f;

    for (int k0 = 0; k0 < K; k0 += 8) {
        float4 a4 = *(const float4*)(Ap + k0);
        float4 b4 = *(const float4*)(Bp + k0);
        As[lc + 0][lr] = a4.x; As[lc + 1][lr] = a4.y;
        As[lc + 2][lr] = a4.z; As[lc + 3][lr] = a4.w;
        Bs[lc + 0][lr] = b4.x; Bs[lc + 1][lr] = b4.y;
        Bs[lc + 2][lr] = b4.z; Bs[lc + 3][lr] = b4.w;
        __syncthreads();
#pragma unroll
        for (int kk = 0; kk < 8; kk++) {
            float a[8], b[8];
            *(float4*)&a[0] = *(const float4*)&As[kk][ty * 8];
            *(float4*)&a[4] = *(const float4*)&As[kk][ty * 8 + 4];
            *(float4*)&b[0] = *(const float4*)&Bs[kk][tx * 8];
            *(float4*)&b[4] = *(const float4*)&Bs[kk][tx * 8 + 4];
#pragma unroll
            for (int i = 0; i < 8; i++)
#pragma unroll
                for (int j = 0; j < 8; j++)
                    acc[i][j] = fmaf(a[i], b[j], acc[i][j]);
        }
        __syncthreads();
    }

#pragma unroll
    for (int i = 0; i < 8; i++) {
        size_t base = ((size_t)(bm * 128 + ty * 8 + i)) * N + bn * 128 + tx * 8;
#pragma unroll
        for (int j = 0; j < 8; j++) {
            float c = acc[i][j];
            if (EPI == 1) c *= __expf(fminf(wptr[base + j], 0.f));
            C[base + j] = c;
        }
    }
}

// ======================================================================================
// GEMM, B-normal layout: C[m,n] = sum_k A[m,k] * B[k,n]
// 64x64 tile, BK=16. M mult of 64, K mult of 16, N mult of 4 (bounds-checked).
// AOP: 0 = plain A; 1 = A(m,k) = x + (x_last - x) * miu_x[k]  (K must equal CDIM)
// EPI: 0 = store; 1 = tanh; 2 = c += p0[n]; 3 = xdd: c = x + (x_last - x)*(p2[n] + c) (N==CDIM)
// ======================================================================================
template <int AOP, int EPI>
__global__ void __launch_bounds__(256) sgemm_bn(
    const float* __restrict__ A, const float* __restrict__ B, float* __restrict__ C,
    int M, int N, int K,
    const float* __restrict__ p0, const float* __restrict__ p1, const float* __restrict__ p2)
{
    __shared__ float As[16][68];
    __shared__ float Bs[16][64];
    const int tid = threadIdx.x;
    const int bm = blockIdx.y, bn = blockIdx.x;
    const int arow = tid >> 2, acol = (tid & 3) << 2;  // 64 rows x 16 k
    const int brow = tid >> 4, bcol = (tid & 15) << 2; // 16 k x 64 cols
    const int tx = tid & 15, ty = tid >> 4;
    const int gm_a = bm * 64 + arow;
    const int gn_b = bn * 64 + bcol;

    float acc[4][4];
#pragma unroll
    for (int i = 0; i < 4; i++)
#pragma unroll
        for (int j = 0; j < 4; j++) acc[i][j] = 0.f;

    for (int k0 = 0; k0 < K; k0 += 16) {
        float4 a4;
        if (AOP == 0) {
            a4 = *(const float4*)(A + (size_t)gm_a * K + k0 + acol);
        } else {
            float4 xv  = *(const float4*)(p0 + (size_t)gm_a * K + k0 + acol);
            float4 xlv = *(const float4*)(p1 + (size_t)gm_a * K + k0 + acol);
            float4 mv  = *(const float4*)(p2 + k0 + acol);
            a4.x = xv.x + (xlv.x - xv.x) * mv.x;
            a4.y = xv.y + (xlv.y - xv.y) * mv.y;
            a4.z = xv.z + (xlv.z - xv.z) * mv.z;
            a4.w = xv.w + (xlv.w - xv.w) * mv.w;
        }
        As[acol + 0][arow] = a4.x; As[acol + 1][arow] = a4.y;
        As[acol + 2][arow] = a4.z; As[acol + 3][arow] = a4.w;

        float4 b4 = make_float4(0.f, 0.f, 0.f, 0.f);
        if (gn_b < N)
            b4 = *(const float4*)(B + (size_t)(k0 + brow) * N + gn_b);
        Bs[brow][bcol + 0] = b4.x; Bs[brow][bcol + 1] = b4.y;
        Bs[brow][bcol + 2] = b4.z; Bs[brow][bcol + 3] = b4.w;
        __syncthreads();
#pragma unroll
        for (int kk = 0; kk < 16; kk++) {
            float4 a = *(const float4*)&As[kk][ty * 4];
            float4 b = *(const float4*)&Bs[kk][tx * 4];
            acc[0][0] = fmaf(a.x, b.x, acc[0][0]); acc[0][1] = fmaf(a.x, b.y, acc[0][1]);
            acc[0][2] = fmaf(a.x, b.z, acc[0][2]); acc[0][3] = fmaf(a.x, b.w, acc[0][3]);
            acc[1][0] = fmaf(a.y, b.x, acc[1][0]); acc[1][1] = fmaf(a.y, b.y, acc[1][1]);
            acc[1][2] = fmaf(a.y, b.z, acc[1][2]); acc[1][3] = fmaf(a.y, b.w, acc[1][3]);
            acc[2][0] = fmaf(a.z, b.x, acc[2][0]); acc[2][1] = fmaf(a.z, b.y, acc[2][1]);
            acc[2][2] = fmaf(a.z, b.z, acc[2][2]); acc[2][3] = fmaf(a.z, b.w, acc[2][3]);
            acc[3][0] = fmaf(a.w, b.x, acc[3][0]); acc[3][1] = fmaf(a.w, b.y, acc[3][1]);
            acc[3][2] = fmaf(a.w, b.z, acc[3][2]); acc[3][3] = fmaf(a.w, b.w, acc[3][3]);
        }
        __syncthreads();
    }

#pragma unroll
    for (int i = 0; i < 4; i++) {
        int m = bm * 64 + ty * 4 + i;
#pragma unroll
        for (int j = 0; j < 4; j++) {
            int n = bn * 64 + tx * 4 + j;
            if (n >= N) continue;
            float c = acc[i][j];
            if (EPI == 1) c = tanhf(c);
            else if (EPI == 2) c += p0[n];
            else if (EPI == 3) {
                size_t ix = (size_t)m * N + n;   // N == CDIM here
                float xv = p0[ix], xlv = p1[ix];
                c = xv + (xlv - xv) * (p2[n] + c);
            }
            C[(size_t)m * N + n] = c;
        }
    }
}

// ======================================================================================
// WKV-6 scan. Grid = B*H blocks, 256 threads.
// Thread (i = tid&63, jg = tid>>6) owns state[j0..j0+15][i] in registers.
// y_i = sum_j r_j*state[j,i]  +  v_i * (sum_j r_j*u_j*k_j)
// state[j,i] = exp(-exp(w_j))*state[j,i] + k_j*v_i
// ======================================================================================
__global__ void __launch_bounds__(256) wkv_kernel(
    const float* __restrict__ r, const float* __restrict__ k,
    const float* __restrict__ v, const float* __restrict__ w,
    const float* __restrict__ u, const float* __restrict__ s_in,
    float* __restrict__ y, float* __restrict__ s_out)
{
    const int bh = blockIdx.x;
    const int b = bh >> 4, h = bh & 15;
    const int tid = threadIdx.x;
    const int i  = tid & 63;
    const int jg = tid >> 6;
    const int j0 = jg * 16;

    __shared__ float rs[64], ks[64], ds[64], vs[64];
    __shared__ float cs[2];
    __shared__ float ypart[4][64];

    float st[16];
    size_t sbase = (((size_t)b * HNUM + h) * DDIM + j0) * DDIM + i;
#pragma unroll
    for (int q = 0; q < 16; q++) st[q] = s_in[sbase + (size_t)q * DDIM];

    float uj = 0.f;
    if (tid < 64) uj = u[h * DDIM + tid];

    size_t off = (((size_t)b * TSEQ) * HNUM + h) * DDIM;

    for (int t = 0; t < TSEQ; t++, off += HNUM * DDIM) {
        if (tid < 64) {
            float rv = r[off + tid];
            float kv = k[off + tid];
            float wv = w[off + tid];
            float vv = v[off + tid];
            rs[tid] = rv; ks[tid] = kv; vs[tid] = vv;
            ds[tid] = __expf(-__expf(wv));
            float p = rv * uj * kv;
#pragma unroll
            for (int s = 16; s > 0; s >>= 1)
                p += __shfl_down_sync(0xffffffffu, p, s);
            if ((tid & 31) == 0) cs[tid >> 5] = p;
        }
        __syncthreads();

        const float vi = vs[i];
        float acc = 0.f;
#pragma unroll
        for (int q = 0; q < 16; q += 4) {
            float4 r4 = *(const float4*)&rs[j0 + q];
            float4 k4 = *(const float4*)&ks[j0 + q];
            float4 d4 = *(const float4*)&ds[j0 + q];
            acc = fmaf(r4.x, st[q + 0], acc); st[q + 0] = fmaf(d4.x, st[q + 0], k4.x * vi);
            acc = fmaf(r4.y, st[q + 1], acc); st[q + 1] = fmaf(d4.y, st[q + 1], k4.y * vi);
            acc = fmaf(r4.z, st[q + 2], acc); st[q + 2] = fmaf(d4.z, st[q + 2], k4.z * vi);
            acc = fmaf(r4.w, st[q + 3], acc); st[q + 3] = fmaf(d4.w, st[q + 3], k4.w * vi);
        }
        ypart[jg][i] = acc;
        __syncthreads();

        if (tid < 64) {
            float yv = ypart[0][tid] + ypart[1][tid] + ypart[2][tid] + ypart[3][tid]
                     + vs[tid] * (cs[0] + cs[1]);
            y[off + tid] = yv;
        }
    }

#pragma unroll
    for (int q = 0; q < 16; q++) s_out[sbase + (size_t)q * DDIM] = st[q];
}

// ======================================================================================
// GroupNorm (groups = heads, D=64, eps = 1e-5*H) fused with *g, in-place on y.
// One warp per (m, h) group.
// ======================================================================================
__global__ void __launch_bounds__(256) gn_kernel(
    float* __restrict__ y, const float* __restrict__ g,
    const float* __restrict__ gamma, const float* __restrict__ beta)
{
    int warp = (blockIdx.x * blockDim.x + threadIdx.x) >> 5;
    int lane = threadIdx.x & 31;
    int m = warp >> 4, h = warp & 15;
    size_t base = (size_t)m * CDIM + h * DDIM;

    float2 vv = *(const float2*)&y[base + lane * 2];
    float s  = vv.x + vv.y;
    float sq = vv.x * vv.x + vv.y * vv.y;
#pragma unroll
    for (int o = 16; o > 0; o >>= 1) {
        s  += __shfl_xor_sync(0xffffffffu, s,  o);
        sq += __shfl_xor_sync(0xffffffffu, sq, o);
    }
    float mean = s * (1.f / 64.f);
    float var  = sq * (1.f / 64.f) - mean * mean;
    float inv  = rsqrtf(var + 1e-5f * (float)HNUM);

    int c0 = h * DDIM + lane * 2;
    float2 gv = *(const float2*)&g[base + lane * 2];
    float o0 = ((vv.x - mean) * inv * gamma[c0]     + beta[c0])     * gv.x;
    float o1 = ((vv.y - mean) * inv * gamma[c0 + 1] + beta[c0 + 1]) * gv.y;
    *(float2*)&y[base + lane * 2] = make_float2(o0, o1);
}

__global__ void __launch_bounds__(256) copy_kernel(
    const float4* __restrict__ src, float4* __restrict__ dst, int n4)
{
    int idx = blockIdx.x * blockDim.x + threadIdx.x;
    if (idx < n4) dst[idx] = src[idx];
}

// ======================================================================================
extern "C" void kernel_launch(void* const* d_in, const int* in_sizes, int n_in,
                              void* d_out, int out_size)
{
    const float* x    = (const float*)d_in[0];
    const float* xlst = (const float*)d_in[1];
    const float* s_in = (const float*)d_in[2];
    const float* miux = (const float*)d_in[3];
    const float* lam  = (const float*)d_in[4];
    const float* Aw   = (const float*)d_in[5];
    const float* Blo  = (const float*)d_in[6];
    const float* tdm  = (const float*)d_in[7];
    const float* tdA  = (const float*)d_in[8];
    const float* tdB  = (const float*)d_in[9];
    const float* u    = (const float*)d_in[10];
    const float* Wk   = (const float*)d_in[11];
    const float* Wv   = (const float*)d_in[12];
    const float* Wr   = (const float*)d_in[13];
    const float* Wo   = (const float*)d_in[14];
    const float* Wg1  = (const float*)d_in[15];
    const float* Wg2  = (const float*)d_in[16];
    const float* gam  = (const float*)d_in[17];
    const float* bet  = (const float*)d_in[18];
    float* out = (float*)d_out;

    float *t1, *xdd, *h1, *w, *kb, *vb, *rb, *gb, *yb, *g1;
    cudaGetSymbolAddress((void**)&t1,  g_t1);
    cudaGetSymbolAddress((void**)&xdd, g_xdd);
    cudaGetSymbolAddress((void**)&h1,  g_h1);
    cudaGetSymbolAddress((void**)&w,   g_w);
    cudaGetSymbolAddress((void**)&kb,  g_kb);
    cudaGetSymbolAddress((void**)&vb,  g_vb);
    cudaGetSymbolAddress((void**)&rb,  g_rb);
    cudaGetSymbolAddress((void**)&gb,  g_gb);
    cudaGetSymbolAddress((void**)&yb,  g_yb);
    cudaGetSymbolAddress((void**)&g1,  g_g1);

    const size_t MC = (size_t)MROWS * CDIM;
    dim3 thr(256);

    // 1) t1 = tanh(xl @ A),  xl fused from x/x_last/miu_x.  (16384 x 160, K=1024)
    sgemm_bn<1, 1><<<dim3(3, MROWS / 64), thr>>>(x, Aw, t1, MROWS, 160, CDIM, x, xlst, miux);

    // 2) xdd[f] = x + (x_last - x) * (lambda_f + t1_f @ B_lora_f)   (K=32)
    for (int f = 0; f < 5; f++)
        sgemm_bn<0, 3><<<dim3(CDIM / 64, MROWS / 64), thr>>>(
            t1 + (size_t)f * MROWS * 32, Blo + (size_t)f * 32 * CDIM, xdd + (size_t)f * MC,
            MROWS, CDIM, 32, x, xlst, lam + f * CDIM);

    const float* w0 = xdd + 0 * MC;
    const float* k0 = xdd + 1 * MC;
    const float* v0 = xdd + 2 * MC;
    const float* r0 = xdd + 3 * MC;
    const float* g0 = xdd + 4 * MC;

    // 3) h1 = tanh(w0 @ td_A)        (16384 x 64, K=1024)
    sgemm_bn<0, 1><<<dim3(1, MROWS / 64), thr>>>(w0, tdA, h1, MROWS, 64, CDIM, nullptr, nullptr, nullptr);
    // 4) w = time_decay_miu + h1 @ td_B   (16384 x 1024, K=64)
    sgemm_bn<0, 2><<<dim3(CDIM / 64, MROWS / 64), thr>>>(h1, tdB, w, MROWS, CDIM, 64, tdm, nullptr, nullptr);

    // 5) k = (k0 @ Wk^T) * exp(min(w,0))
    sgemm_bt<1><<<dim3(CDIM / 128, MROWS / 128), thr>>>(k0, Wk, kb, MROWS, CDIM, CDIM, w);
    // 6) v = v0 @ Wv^T ;  7) r = r0 @ Wr^T
    sgemm_bt<0><<<dim3(CDIM / 128, MROWS / 128), thr>>>(v0, Wv, vb, MROWS, CDIM, CDIM, nullptr);
    sgemm_bt<0><<<dim3(CDIM / 128, MROWS / 128), thr>>>(r0, Wr, rb, MROWS, CDIM, CDIM, nullptr);

    // 8) g1 = tanh(g0 @ W_g1) (N=160, K=1024);  9) g = g1 @ W_g2 (N=1024, K=160)
    sgemm_bn<0, 1><<<dim3(3, MROWS / 64), thr>>>(g0, Wg1, g1, MROWS, 160, CDIM, nullptr, nullptr, nullptr);
    sgemm_bn<0, 0><<<dim3(CDIM / 64, MROWS / 64), thr>>>(g1, Wg2, gb, MROWS, CDIM, 160, nullptr, nullptr, nullptr);

    // 10) WKV-6 scan -> y, s_new (s_new straight into d_out)
    wkv_kernel<<<BSZ * HNUM, 256>>>(rb, kb, vb, w, u, s_in, yb, out + 2 * MC);

    // 11) GroupNorm * g, in place on y
    gn_kernel<<<(MROWS * HNUM) / 8, 256>>>(yb, gb, gam, bet);

    // 12) out = (yn*g) @ Wo^T -> d_out[0 : M*C]
    sgemm_bt<0><<<dim3(CDIM / 128, MROWS / 128), thr>>>(yb, Wo, out, MROWS, CDIM, CDIM, nullptr);

    // 13) x_raw passthrough -> d_out[M*C : 2*M*C]
    copy_kernel<<<(int)(MC / 4 / 256), 256>>>((const float4*)x, (float4*)(out + MC), (int)(MC / 4));
}

// round 3
// speedup vs baseline: 1.5351x; 1.5351x over previous
#include <cuda_runtime.h>
#include <cuda_bf16.h>
#include <stdint.h>
#include <math.h>

#define MROWS 16384   // B*T = 8*2048
#define CDIM  1024
#define HNUM  16
#define DDIM  64
#define TSEQ  2048
#define BSZ   8

// ---------------- scratch (static device memory; no runtime allocation) ----------------
__device__ float g_t1 [(size_t)MROWS * 160];
__device__ float g_xdd[5][(size_t)MROWS * CDIM];
__device__ float g_h1 [(size_t)MROWS * 64];
__device__ float g_w  [(size_t)MROWS * CDIM];
__device__ float g_kb [(size_t)MROWS * CDIM];
__device__ float g_vb [(size_t)MROWS * CDIM];
__device__ float g_rb [(size_t)MROWS * CDIM];
__device__ float g_gb [(size_t)MROWS * CDIM];
__device__ float g_yb [(size_t)MROWS * CDIM];
__device__ float g_g1 [(size_t)MROWS * 160];

// ======================================================================================
// mma.sync helpers (sm_80+ baseline; no 'a'-suffix features)
// ======================================================================================
__device__ __forceinline__ uint32_t smem_u32(const void* p) {
    uint32_t a;
    asm("{ .reg .u64 t; cvta.to.shared.u64 t, %1; cvt.u32.u64 %0, t; }" : "=r"(a) : "l"(p));
    return a;
}
__device__ __forceinline__ void ldsm4(uint32_t* r, uint32_t addr) {
    asm volatile("ldmatrix.sync.aligned.m8n8.x4.shared.b16 {%0,%1,%2,%3}, [%4];"
        : "=r"(r[0]), "=r"(r[1]), "=r"(r[2]), "=r"(r[3]) : "r"(addr));
}
__device__ __forceinline__ void mma16816(float* c, const uint32_t* a, const uint32_t* b) {
    asm volatile("mma.sync.aligned.m16n8k16.row.col.f32.bf16.bf16.f32 "
        "{%0,%1,%2,%3}, {%4,%5,%6,%7}, {%8,%9}, {%0,%1,%2,%3};"
        : "+f"(c[0]), "+f"(c[1]), "+f"(c[2]), "+f"(c[3])
        : "r"(a[0]), "r"(a[1]), "r"(a[2]), "r"(a[3]), "r"(b[0]), "r"(b[1]));
}
__device__ __forceinline__ void cvt_hilo(float4 v, uint2& hi, uint2& lo) {
    __nv_bfloat16 h0 = __float2bfloat16(v.x), h1 = __float2bfloat16(v.y);
    __nv_bfloat16 h2 = __float2bfloat16(v.z), h3 = __float2bfloat16(v.w);
    __nv_bfloat16 l0 = __float2bfloat16(v.x - __bfloat162float(h0));
    __nv_bfloat16 l1 = __float2bfloat16(v.y - __bfloat162float(h1));
    __nv_bfloat16 l2 = __float2bfloat16(v.z - __bfloat162float(h2));
    __nv_bfloat16 l3 = __float2bfloat16(v.w - __bfloat162float(h3));
    __nv_bfloat162 H01 = __halves2bfloat162(h0, h1), H23 = __halves2bfloat162(h2, h3);
    __nv_bfloat162 L01 = __halves2bfloat162(l0, l1), L23 = __halves2bfloat162(l2, l3);
    hi = make_uint2(*(uint32_t*)&H01, *(uint32_t*)&H23);
    lo = make_uint2(*(uint32_t*)&L01, *(uint32_t*)&L23);
}

// ======================================================================================
// HMMA GEMM (bf16x3 split): C[m,n] = sum_k A[m,k]*B[n,k], fp32 in/out.
// M=16384, N=1024, K=1024 fixed. Tile 128x128, BK=32, 8 warps @ 32m x 64n.
// EPI: 0 = plain, 1 = c *= exp(min(w[m,n],0))
// ======================================================================================
#define SPITCH 40   // bf16 elements per smem row (32 + 8 pad -> 80B rows, ldmatrix conflict-free)

template <int EPI>
__global__ void __launch_bounds__(256) mma_gemm_bt(
    const float* __restrict__ A, const float* __restrict__ B, float* __restrict__ C,
    const float* __restrict__ wptr)
{
    __shared__ __nv_bfloat16 Ahi[128][SPITCH], Alo[128][SPITCH];
    __shared__ __nv_bfloat16 Bhi[128][SPITCH], Blo[128][SPITCH];

    const int tid = threadIdx.x, wid = tid >> 5, lane = tid & 31;
    const int bm = blockIdx.y, bn = blockIdx.x;
    const int wm = wid & 3;   // m quarter -> rows wm*32
    const int wn = wid >> 2;  // n half   -> cols wn*64

    const int lrow = tid >> 3;          // 0..31
    const int lcol = (tid & 7) * 4;     // 0..28

    const float* Ab = A + ((size_t)(bm * 128 + lrow)) * CDIM + lcol;
    const float* Bb = B + ((size_t)(bn * 128 + lrow)) * CDIM + lcol;

    float acc[2][8][4];
#pragma unroll
    for (int i = 0; i < 2; i++)
#pragma unroll
        for (int j = 0; j < 8; j++)
#pragma unroll
            for (int q = 0; q < 4; q++) acc[i][j][q] = 0.f;

    // ldmatrix source addresses (fixed per thread, k-offset added per step)
    const uint32_t sAhi = smem_u32(&Ahi[0][0]), sAlo = smem_u32(&Alo[0][0]);
    const uint32_t sBhi = smem_u32(&Bhi[0][0]), sBlo = smem_u32(&Blo[0][0]);
    const int arow = wm * 32 + (lane & 7) + ((lane >> 3) & 1) * 8;   // + mt*16
    const int acol8 = (lane >> 4) * 8;
    const int brow = wn * 64 + ((lane >> 4) << 3) + (lane & 7);      // + nt2*16
    const int bcol8 = ((lane >> 3) & 1) * 8;

    float4 ra[4], rb[4];
#pragma unroll
    for (int p = 0; p < 4; p++) {
        ra[p] = *(const float4*)(Ab + (size_t)(p * 32) * CDIM);
        rb[p] = *(const float4*)(Bb + (size_t)(p * 32) * CDIM);
    }

    for (int c = 0; c < CDIM / 32; c++) {
        __syncthreads();
#pragma unroll
        for (int p = 0; p < 4; p++) {
            uint2 hi, lo;
            cvt_hilo(ra[p], hi, lo);
            *(uint2*)&Ahi[p * 32 + lrow][lcol] = hi;
            *(uint2*)&Alo[p * 32 + lrow][lcol] = lo;
            cvt_hilo(rb[p], hi, lo);
            *(uint2*)&Bhi[p * 32 + lrow][lcol] = hi;
            *(uint2*)&Blo[p * 32 + lrow][lcol] = lo;
        }
        __syncthreads();

        if (c + 1 < CDIM / 32) {
            const int k0 = (c + 1) * 32;
#pragma unroll
            for (int p = 0; p < 4; p++) {
                ra[p] = *(const float4*)(Ab + (size_t)(p * 32) * CDIM + k0);
                rb[p] = *(const float4*)(Bb + (size_t)(p * 32) * CDIM + k0);
            }
        }

#pragma unroll
        for (int ks = 0; ks < 2; ks++) {
            const int kc = ks * 16;
            uint32_t ah[2][4], al[2][4], bh[8][2], bl[8][2];
#pragma unroll
            for (int mt = 0; mt < 2; mt++) {
                uint32_t off = (uint32_t)((arow + mt * 16) * SPITCH + kc + acol8) * 2;
                ldsm4(ah[mt], sAhi + off);
                ldsm4(al[mt], sAlo + off);
            }
#pragma unroll
            for (int nt2 = 0; nt2 < 4; nt2++) {
                uint32_t off = (uint32_t)((brow + nt2 * 16) * SPITCH + kc + bcol8) * 2;
                uint32_t r[4];
                ldsm4(r, sBhi + off);
                bh[nt2 * 2][0] = r[0]; bh[nt2 * 2][1] = r[1];
                bh[nt2 * 2 + 1][0] = r[2]; bh[nt2 * 2 + 1][1] = r[3];
                ldsm4(r, sBlo + off);
                bl[nt2 * 2][0] = r[0]; bl[nt2 * 2][1] = r[1];
                bl[nt2 * 2 + 1][0] = r[2]; bl[nt2 * 2 + 1][1] = r[3];
            }
#pragma unroll
            for (int mt = 0; mt < 2; mt++)
#pragma unroll
                for (int nt = 0; nt < 8; nt++) {
                    mma16816(acc[mt][nt], ah[mt], bh[nt]);
                    mma16816(acc[mt][nt], ah[mt], bl[nt]);
                    mma16816(acc[mt][nt], al[mt], bh[nt]);
                }
        }
    }

    // ---- epilogue ----
#pragma unroll
    for (int mt = 0; mt < 2; mt++) {
        const int m = bm * 128 + wm * 32 + mt * 16 + (lane >> 2);
#pragma unroll
        for (int nt = 0; nt < 8; nt++) {
            const int n = bn * 128 + wn * 64 + nt * 8 + (lane & 3) * 2;
            size_t i0 = (size_t)m * CDIM + n;
            size_t i1 = (size_t)(m + 8) * CDIM + n;
            float c0 = acc[mt][nt][0], c1 = acc[mt][nt][1];
            float c2 = acc[mt][nt][2], c3 = acc[mt][nt][3];
            if (EPI == 1) {
                c0 *= __expf(fminf(wptr[i0], 0.f));
                c1 *= __expf(fminf(wptr[i0 + 1], 0.f));
                c2 *= __expf(fminf(wptr[i1], 0.f));
                c3 *= __expf(fminf(wptr[i1 + 1], 0.f));
            }
            *(float2*)(C + i0) = make_float2(c0, c1);
            *(float2*)(C + i1) = make_float2(c2, c3);
        }
    }
}

// ======================================================================================
// GEMM, B-normal layout: C[m,n] = sum_k A[m,k] * B[k,n]  (small-N / small-K cases)
// ======================================================================================
template <int AOP, int EPI>
__global__ void __launch_bounds__(256) sgemm_bn(
    const float* __restrict__ A, const float* __restrict__ B, float* __restrict__ C,
    int M, int N, int K,
    const float* __restrict__ p0, const float* __restrict__ p1, const float* __restrict__ p2)
{
    __shared__ float As[16][68];
    __shared__ float Bs[16][64];
    const int tid = threadIdx.x;
    const int bm = blockIdx.y, bn = blockIdx.x;
    const int arow = tid >> 2, acol = (tid & 3) << 2;
    const int brow = tid >> 4, bcol = (tid & 15) << 2;
    const int tx = tid & 15, ty = tid >> 4;
    const int gm_a = bm * 64 + arow;
    const int gn_b = bn * 64 + bcol;

    float acc[4][4];
#pragma unroll
    for (int i = 0; i < 4; i++)
#pragma unroll
        for (int j = 0; j < 4; j++) acc[i][j] = 0.f;

    for (int k0 = 0; k0 < K; k0 += 16) {
        float4 a4;
        if (AOP == 0) {
            a4 = *(const float4*)(A + (size_t)gm_a * K + k0 + acol);
        } else {
            float4 xv  = *(const float4*)(p0 + (size_t)gm_a * K + k0 + acol);
            float4 xlv = *(const float4*)(p1 + (size_t)gm_a * K + k0 + acol);
            float4 mv  = *(const float4*)(p2 + k0 + acol);
            a4.x = xv.x + (xlv.x - xv.x) * mv.x;
            a4.y = xv.y + (xlv.y - xv.y) * mv.y;
            a4.z = xv.z + (xlv.z - xv.z) * mv.z;
            a4.w = xv.w + (xlv.w - xv.w) * mv.w;
        }
        As[acol + 0][arow] = a4.x; As[acol + 1][arow] = a4.y;
        As[acol + 2][arow] = a4.z; As[acol + 3][arow] = a4.w;

        float4 b4 = make_float4(0.f, 0.f, 0.f, 0.f);
        if (gn_b < N)
            b4 = *(const float4*)(B + (size_t)(k0 + brow) * N + gn_b);
        Bs[brow][bcol + 0] = b4.x; Bs[brow][bcol + 1] = b4.y;
        Bs[brow][bcol + 2] = b4.z; Bs[brow][bcol + 3] = b4.w;
        __syncthreads();
#pragma unroll
        for (int kk = 0; kk < 16; kk++) {
            float4 a = *(const float4*)&As[kk][ty * 4];
            float4 b = *(const float4*)&Bs[kk][tx * 4];
            acc[0][0] = fmaf(a.x, b.x, acc[0][0]); acc[0][1] = fmaf(a.x, b.y, acc[0][1]);
            acc[0][2] = fmaf(a.x, b.z, acc[0][2]); acc[0][3] = fmaf(a.x, b.w, acc[0][3]);
            acc[1][0] = fmaf(a.y, b.x, acc[1][0]); acc[1][1] = fmaf(a.y, b.y, acc[1][1]);
            acc[1][2] = fmaf(a.y, b.z, acc[1][2]); acc[1][3] = fmaf(a.y, b.w, acc[1][3]);
            acc[2][0] = fmaf(a.z, b.x, acc[2][0]); acc[2][1] = fmaf(a.z, b.y, acc[2][1]);
            acc[2][2] = fmaf(a.z, b.z, acc[2][2]); acc[2][3] = fmaf(a.z, b.w, acc[2][3]);
            acc[3][0] = fmaf(a.w, b.x, acc[3][0]); acc[3][1] = fmaf(a.w, b.y, acc[3][1]);
            acc[3][2] = fmaf(a.w, b.z, acc[3][2]); acc[3][3] = fmaf(a.w, b.w, acc[3][3]);
        }
        __syncthreads();
    }

#pragma unroll
    for (int i = 0; i < 4; i++) {
        int m = bm * 64 + ty * 4 + i;
#pragma unroll
        for (int j = 0; j < 4; j++) {
            int n = bn * 64 + tx * 4 + j;
            if (n >= N) continue;
            float c = acc[i][j];
            if (EPI == 1) c = tanhf(c);
            else if (EPI == 2) c += p0[n];
            else if (EPI == 3) {
                size_t ix = (size_t)m * N + n;
                float xv = p0[ix], xlv = p1[ix];
                c = xv + (xlv - xv) * (p2[n] + c);
            }
            C[(size_t)m * N + n] = c;
        }
    }
}

// ======================================================================================
// WKV-6 scan
// ======================================================================================
__global__ void __launch_bounds__(256) wkv_kernel(
    const float* __restrict__ r, const float* __restrict__ k,
    const float* __restrict__ v, const float* __restrict__ w,
    const float* __restrict__ u, const float* __restrict__ s_in,
    float* __restrict__ y, float* __restrict__ s_out)
{
    const int bh = blockIdx.x;
    const int b = bh >> 4, h = bh & 15;
    const int tid = threadIdx.x;
    const int i  = tid & 63;
    const int jg = tid >> 6;
    const int j0 = jg * 16;

    __shared__ float rs[64], ks[64], ds[64], vs[64];
    __shared__ float cs[2];
    __shared__ float ypart[4][64];

    float st[16];
    size_t sbase = (((size_t)b * HNUM + h) * DDIM + j0) * DDIM + i;
#pragma unroll
    for (int q = 0; q < 16; q++) st[q] = s_in[sbase + (size_t)q * DDIM];

    float uj = 0.f;
    if (tid < 64) uj = u[h * DDIM + tid];

    size_t off = (((size_t)b * TSEQ) * HNUM + h) * DDIM;

    for (int t = 0; t < TSEQ; t++, off += HNUM * DDIM) {
        if (tid < 64) {
            float rv = r[off + tid];
            float kv = k[off + tid];
            float wv = w[off + tid];
            float vv = v[off + tid];
            rs[tid] = rv; ks[tid] = kv; vs[tid] = vv;
            ds[tid] = __expf(-__expf(wv));
            float p = rv * uj * kv;
#pragma unroll
            for (int s = 16; s > 0; s >>= 1)
                p += __shfl_down_sync(0xffffffffu, p, s);
            if ((tid & 31) == 0) cs[tid >> 5] = p;
        }
        __syncthreads();

        const float vi = vs[i];
        float acc = 0.f;
#pragma unroll
        for (int q = 0; q < 16; q += 4) {
            float4 r4 = *(const float4*)&rs[j0 + q];
            float4 k4 = *(const float4*)&ks[j0 + q];
            float4 d4 = *(const float4*)&ds[j0 + q];
            acc = fmaf(r4.x, st[q + 0], acc); st[q + 0] = fmaf(d4.x, st[q + 0], k4.x * vi);
            acc = fmaf(r4.y, st[q + 1], acc); st[q + 1] = fmaf(d4.y, st[q + 1], k4.y * vi);
            acc = fmaf(r4.z, st[q + 2], acc); st[q + 2] = fmaf(d4.z, st[q + 2], k4.z * vi);
            acc = fmaf(r4.w, st[q + 3], acc); st[q + 3] = fmaf(d4.w, st[q + 3], k4.w * vi);
        }
        ypart[jg][i] = acc;
        __syncthreads();

        if (tid < 64) {
            float yv = ypart[0][tid] + ypart[1][tid] + ypart[2][tid] + ypart[3][tid]
                     + vs[tid] * (cs[0] + cs[1]);
            y[off + tid] = yv;
        }
    }

#pragma unroll
    for (int q = 0; q < 16; q++) s_out[sbase + (size_t)q * DDIM] = st[q];
}

// ======================================================================================
// GroupNorm fused with *g
// ======================================================================================
__global__ void __launch_bounds__(256) gn_kernel(
    float* __restrict__ y, const float* __restrict__ g,
    const float* __restrict__ gamma, const float* __restrict__ beta)
{
    int warp = (blockIdx.x * blockDim.x + threadIdx.x) >> 5;
    int lane = threadIdx.x & 31;
    int m = warp >> 4, h = warp & 15;
    size_t base = (size_t)m * CDIM + h * DDIM;

    float2 vv = *(const float2*)&y[base + lane * 2];
    float s  = vv.x + vv.y;
    float sq = vv.x * vv.x + vv.y * vv.y;
#pragma unroll
    for (int o = 16; o > 0; o >>= 1) {
        s  += __shfl_xor_sync(0xffffffffu, s,  o);
        sq += __shfl_xor_sync(0xffffffffu, sq, o);
    }
    float mean = s * (1.f / 64.f);
    float var  = sq * (1.f / 64.f) - mean * mean;
    float inv  = rsqrtf(var + 1e-5f * (float)HNUM);

    int c0 = h * DDIM + lane * 2;
    float2 gv = *(const float2*)&g[base + lane * 2];
    float o0 = ((vv.x - mean) * inv * gamma[c0]     + beta[c0])     * gv.x;
    float o1 = ((vv.y - mean) * inv * gamma[c0 + 1] + beta[c0 + 1]) * gv.y;
    *(float2*)&y[base + lane * 2] = make_float2(o0, o1);
}

__global__ void __launch_bounds__(256) copy_kernel(
    const float4* __restrict__ src, float4* __restrict__ dst, int n4)
{
    int idx = blockIdx.x * blockDim.x + threadIdx.x;
    if (idx < n4) dst[idx] = src[idx];
}

// ======================================================================================
extern "C" void kernel_launch(void* const* d_in, const int* in_sizes, int n_in,
                              void* d_out, int out_size)
{
    const float* x    = (const float*)d_in[0];
    const float* xlst = (const float*)d_in[1];
    const float* s_in = (const float*)d_in[2];
    const float* miux = (const float*)d_in[3];
    const float* lam  = (const float*)d_in[4];
    const float* Aw   = (const float*)d_in[5];
    const float* Blo  = (const float*)d_in[6];
    const float* tdm  = (const float*)d_in[7];
    const float* tdA  = (const float*)d_in[8];
    const float* tdB  = (const float*)d_in[9];
    const float* u    = (const float*)d_in[10];
    const float* Wk   = (const float*)d_in[11];
    const float* Wv   = (const float*)d_in[12];
    const float* Wr   = (const float*)d_in[13];
    const float* Wo   = (const float*)d_in[14];
    const float* Wg1  = (const float*)d_in[15];
    const float* Wg2  = (const float*)d_in[16];
    const float* gam  = (const float*)d_in[17];
    const float* bet  = (const float*)d_in[18];
    float* out = (float*)d_out;

    float *t1, *xdd, *h1, *w, *kb, *vb, *rb, *gb, *yb, *g1;
    cudaGetSymbolAddress((void**)&t1,  g_t1);
    cudaGetSymbolAddress((void**)&xdd, g_xdd);
    cudaGetSymbolAddress((void**)&h1,  g_h1);
    cudaGetSymbolAddress((void**)&w,   g_w);
    cudaGetSymbolAddress((void**)&kb,  g_kb);
    cudaGetSymbolAddress((void**)&vb,  g_vb);
    cudaGetSymbolAddress((void**)&rb,  g_rb);
    cudaGetSymbolAddress((void**)&gb,  g_gb);
    cudaGetSymbolAddress((void**)&yb,  g_yb);
    cudaGetSymbolAddress((void**)&g1,  g_g1);

    const size_t MC = (size_t)MROWS * CDIM;
    dim3 thr(256);
    dim3 mmaGrid(CDIM / 128, MROWS / 128);

    // 1) t1 = tanh(xl @ A)
    sgemm_bn<1, 1><<<dim3(3, MROWS / 64), thr>>>(x, Aw, t1, MROWS, 160, CDIM, x, xlst, miux);

    // 2) xdd[f] = x + (x_last - x) * (lambda_f + t1_f @ B_lora_f)
    for (int f = 0; f < 5; f++)
        sgemm_bn<0, 3><<<dim3(CDIM / 64, MROWS / 64), thr>>>(
            t1 + (size_t)f * MROWS * 32, Blo + (size_t)f * 32 * CDIM, xdd + (size_t)f * MC,
            MROWS, CDIM, 32, x, xlst, lam + f * CDIM);

    const float* w0 = xdd + 0 * MC;
    const float* k0 = xdd + 1 * MC;
    const float* v0 = xdd + 2 * MC;
    const float* r0 = xdd + 3 * MC;
    const float* g0 = xdd + 4 * MC;

    // 3) h1 = tanh(w0 @ td_A)
    sgemm_bn<0, 1><<<dim3(1, MROWS / 64), thr>>>(w0, tdA, h1, MROWS, 64, CDIM, nullptr, nullptr, nullptr);
    // 4) w = time_decay_miu + h1 @ td_B
    sgemm_bn<0, 2><<<dim3(CDIM / 64, MROWS / 64), thr>>>(h1, tdB, w, MROWS, CDIM, 64, tdm, nullptr, nullptr);

    // 5-7) big projections on tensor cores (bf16x3 via mma.sync)
    mma_gemm_bt<1><<<mmaGrid, thr>>>(k0, Wk, kb, w);
    mma_gemm_bt<0><<<mmaGrid, thr>>>(v0, Wv, vb, nullptr);
    mma_gemm_bt<0><<<mmaGrid, thr>>>(r0, Wr, rb, nullptr);

    // 8-9) gate
    sgemm_bn<0, 1><<<dim3(3, MROWS / 64), thr>>>(g0, Wg1, g1, MROWS, 160, CDIM, nullptr, nullptr, nullptr);
    sgemm_bn<0, 0><<<dim3(CDIM / 64, MROWS / 64), thr>>>(g1, Wg2, gb, MROWS, CDIM, 160, nullptr, nullptr, nullptr);

    // 10) WKV-6 scan -> y, s_new
    wkv_kernel<<<BSZ * HNUM, 256>>>(rb, kb, vb, w, u, s_in, yb, out + 2 * MC);

    // 11) GroupNorm * g
    gn_kernel<<<(MROWS * HNUM) / 8, 256>>>(yb, gb, gam, bet);

    // 12) out = (yn*g) @ Wo^T
    mma_gemm_bt<0><<<mmaGrid, thr>>>(yb, Wo, out, nullptr);

    // 13) x_raw passthrough
    copy_kernel<<<(int)(MC / 4 / 256), 256>>>((const float4*)x, (float4*)(out + MC), (int)(MC / 4));
}

// round 4
// speedup vs baseline: 1.6452x; 1.0717x over previous
#include <cuda_runtime.h>
#include <cuda_bf16.h>
#include <stdint.h>
#include <math.h>

#define MROWS 16384   // B*T = 8*2048
#define CDIM  1024
#define HNUM  16
#define DDIM  64
#define TSEQ  2048
#define BSZ   8

// ---------------- scratch (static device memory; no runtime allocation) ----------------
__device__ float g_t1 [(size_t)MROWS * 160];
__device__ float g_w0 [(size_t)MROWS * CDIM];
__device__ float g_g0 [(size_t)MROWS * CDIM];
__device__ __nv_bfloat16 g_khi[(size_t)MROWS * CDIM], g_klo[(size_t)MROWS * CDIM];
__device__ __nv_bfloat16 g_vhi[(size_t)MROWS * CDIM], g_vlo[(size_t)MROWS * CDIM];
__device__ __nv_bfloat16 g_rhi[(size_t)MROWS * CDIM], g_rlo[(size_t)MROWS * CDIM];
__device__ __nv_bfloat16 g_yhi[(size_t)MROWS * CDIM], g_ylo[(size_t)MROWS * CDIM];
__device__ __nv_bfloat16 g_Whi[4][(size_t)CDIM * CDIM], g_Wlo[4][(size_t)CDIM * CDIM];
__device__ float g_h1 [(size_t)MROWS * 64];
__device__ float g_w  [(size_t)MROWS * CDIM];
__device__ float g_dec[(size_t)MROWS * CDIM];
__device__ float g_kb [(size_t)MROWS * CDIM];
__device__ float g_vb [(size_t)MROWS * CDIM];
__device__ float g_rb [(size_t)MROWS * CDIM];
__device__ float g_gb [(size_t)MROWS * CDIM];
__device__ float g_yb [(size_t)MROWS * CDIM];
__device__ float g_g1 [(size_t)MROWS * 160];
__device__ float g_cv [(size_t)MROWS * HNUM];

// ======================================================================================
// helpers
// ======================================================================================
__device__ __forceinline__ uint32_t smem_u32(const void* p) {
    uint32_t a;
    asm("{ .reg .u64 t; cvta.to.shared.u64 t, %1; cvt.u32.u64 %0, t; }" : "=r"(a) : "l"(p));
    return a;
}
__device__ __forceinline__ void ldsm4(uint32_t* r, uint32_t addr) {
    asm volatile("ldmatrix.sync.aligned.m8n8.x4.shared.b16 {%0,%1,%2,%3}, [%4];"
        : "=r"(r[0]), "=r"(r[1]), "=r"(r[2]), "=r"(r[3]) : "r"(addr));
}
__device__ __forceinline__ void mma16816(float* c, const uint32_t* a, const uint32_t* b) {
    asm volatile("mma.sync.aligned.m16n8k16.row.col.f32.bf16.bf16.f32 "
        "{%0,%1,%2,%3}, {%4,%5,%6,%7}, {%8,%9}, {%0,%1,%2,%3};"
        : "+f"(c[0]), "+f"(c[1]), "+f"(c[2]), "+f"(c[3])
        : "r"(a[0]), "r"(a[1]), "r"(a[2]), "r"(a[3]), "r"(b[0]), "r"(b[1]));
}
#define CP16(d, s) asm volatile("cp.async.cg.shared.global [%0], [%1], 16;" :: "r"(d), "l"(s))
#define CPCOMMIT() asm volatile("cp.async.commit_group;" ::: "memory")
#define CPWAIT1()  asm volatile("cp.async.wait_group 1;" ::: "memory")

__device__ __forceinline__ void cvt_hilo4(float4 v, uint2& hi, uint2& lo) {
    __nv_bfloat16 h0 = __float2bfloat16(v.x), h1 = __float2bfloat16(v.y);
    __nv_bfloat16 h2 = __float2bfloat16(v.z), h3 = __float2bfloat16(v.w);
    __nv_bfloat16 l0 = __float2bfloat16(v.x - __bfloat162float(h0));
    __nv_bfloat16 l1 = __float2bfloat16(v.y - __bfloat162float(h1));
    __nv_bfloat16 l2 = __float2bfloat16(v.z - __bfloat162float(h2));
    __nv_bfloat16 l3 = __float2bfloat16(v.w - __bfloat162float(h3));
    __nv_bfloat162 H01 = __halves2bfloat162(h0, h1), H23 = __halves2bfloat162(h2, h3);
    __nv_bfloat162 L01 = __halves2bfloat162(l0, l1), L23 = __halves2bfloat162(l2, l3);
    hi = make_uint2(*(uint32_t*)&H01, *(uint32_t*)&H23);
    lo = make_uint2(*(uint32_t*)&L01, *(uint32_t*)&L23);
}

// ======================================================================================
// weight split: fp32 -> bf16 hi/lo
// ======================================================================================
__global__ void __launch_bounds__(256) split_kernel(
    const float4* __restrict__ src, __nv_bfloat16* __restrict__ hi,
    __nv_bfloat16* __restrict__ lo, int n4)
{
    int idx = blockIdx.x * 256 + threadIdx.x;
    if (idx >= n4) return;
    uint2 h, l;
    cvt_hilo4(src[idx], h, l);
    *(uint2*)(hi + (size_t)idx * 4) = h;
    *(uint2*)(lo + (size_t)idx * 4) = l;
}

// ======================================================================================
// bf16x3 HMMA GEMM with cp.async 3-stage pipeline.
// C[m,n] = sum_k A[m,k]*B[n,k]; A,B given as bf16 hi/lo pairs (K=1024, N=1024, M=16384).
// Tile 128m x 256n, BK=32. EPI: 0 plain, 1 = *exp(min(w,0))
// ======================================================================================
#define GP    40            // smem pitch in bf16 (80 B rows -> ldmatrix conflict-free)
#define STGB  61440         // bytes per stage: (128+128)A + 2*256 B rows... (2*5120+2*10240)*2
#define OALO  10240
#define OBHI  20480
#define OBLO  40960

template <int EPI>
__global__ void __launch_bounds__(256, 1) mma_gemm16(
    const __nv_bfloat16* __restrict__ Ahi, const __nv_bfloat16* __restrict__ Alo,
    const __nv_bfloat16* __restrict__ Bhi, const __nv_bfloat16* __restrict__ Blo,
    float* __restrict__ C, const float* __restrict__ wptr)
{
    extern __shared__ char smem[];
    const int tid = threadIdx.x, wid = tid >> 5, lane = tid & 31;
    const int bm = blockIdx.y, bn = blockIdx.x;
    const uint32_t sbase = smem_u32(smem);

    const int q = tid & 3, r0 = tid >> 2;         // loader: row r0(0..63), 16B quarter q
    const __nv_bfloat16* pAhi = Ahi + (size_t)(bm * 128 + r0) * CDIM + q * 8;
    const __nv_bfloat16* pAlo = Alo + (size_t)(bm * 128 + r0) * CDIM + q * 8;
    const __nv_bfloat16* pBhi = Bhi + (size_t)(bn * 256 + r0) * CDIM + q * 8;
    const __nv_bfloat16* pBlo = Blo + (size_t)(bn * 256 + r0) * CDIM + q * 8;
    const uint32_t dA = (uint32_t)(r0 * 80 + q * 16);

    auto issue = [&](int s, int k0) {
        uint32_t sb2 = sbase + s * STGB;
        CP16(sb2 + dA,               pAhi + k0);
        CP16(sb2 + dA + 5120,        pAhi + k0 + 64 * CDIM);
        CP16(sb2 + OALO + dA,        pAlo + k0);
        CP16(sb2 + OALO + dA + 5120, pAlo + k0 + 64 * CDIM);
#pragma unroll
        for (int i = 0; i < 4; i++) {
            CP16(sb2 + OBHI + dA + i * 5120, pBhi + k0 + i * 64 * CDIM);
            CP16(sb2 + OBLO + dA + i * 5120, pBlo + k0 + i * 64 * CDIM);
        }
    };

    float acc[2][16][4];
#pragma unroll
    for (int a = 0; a < 2; a++)
#pragma unroll
        for (int b = 0; b < 16; b++)
#pragma unroll
            for (int c = 0; c < 4; c++) acc[a][b][c] = 0.f;

    const int arow = (wid & 3) * 32 + (lane & 7) + ((lane >> 3) & 1) * 8;
    const int acol8 = (lane >> 4) * 8;
    const int brow = (wid >> 2) * 128 + ((lane >> 4) << 3) + (lane & 7);
    const int bcol8 = ((lane >> 3) & 1) * 8;

    issue(0, 0);  CPCOMMIT();
    issue(1, 32); CPCOMMIT();

    for (int c = 0; c < 32; c++) {
        CPWAIT1();
        __syncthreads();
        {
            int cn = c + 2;
            if (cn < 32) issue(cn % 3, cn * 32);
            CPCOMMIT();
        }
        const uint32_t sA = sbase + (c % 3) * STGB;
#pragma unroll
        for (int ks = 0; ks < 2; ks++) {
            const int kc = ks * 16;
            uint32_t ah[2][4], al[2][4];
#pragma unroll
            for (int mt = 0; mt < 2; mt++) {
                uint32_t off = (uint32_t)((arow + mt * 16) * GP + kc + acol8) * 2;
                ldsm4(ah[mt], sA + off);
                ldsm4(al[mt], sA + OALO + off);
            }
#pragma unroll
            for (int nt2 = 0; nt2 < 8; nt2++) {
                uint32_t boff = (uint32_t)((brow + nt2 * 16) * GP + kc + bcol8) * 2;
                uint32_t rh[4], rl[4];
                ldsm4(rh, sA + OBHI + boff);
                ldsm4(rl, sA + OBLO + boff);
#pragma unroll
                for (int mt = 0; mt < 2; mt++) {
                    mma16816(acc[mt][nt2 * 2], ah[mt], rh);
                    mma16816(acc[mt][nt2 * 2], ah[mt], rl);
                    mma16816(acc[mt][nt2 * 2], al[mt], rh);
                    mma16816(acc[mt][nt2 * 2 + 1], ah[mt], rh + 2);
                    mma16816(acc[mt][nt2 * 2 + 1], ah[mt], rl + 2);
                    mma16816(acc[mt][nt2 * 2 + 1], al[mt], rh + 2);
                }
            }
        }
    }

    // epilogue
#pragma unroll
    for (int mt = 0; mt < 2; mt++) {
        const int m = bm * 128 + (wid & 3) * 32 + mt * 16 + (lane >> 2);
#pragma unroll
        for (int nt = 0; nt < 16; nt++) {
            const int n = bn * 256 + (wid >> 2) * 128 + nt * 8 + (lane & 3) * 2;
            size_t i0 = (size_t)m * CDIM + n;
            size_t i1 = i0 + (size_t)8 * CDIM;
            float c0 = acc[mt][nt][0], c1 = acc[mt][nt][1];
            float c2 = acc[mt][nt][2], c3 = acc[mt][nt][3];
            if (EPI == 1) {
                float2 wa = *(const float2*)(wptr + i0);
                float2 wb = *(const float2*)(wptr + i1);
                c0 *= __expf(fminf(wa.x, 0.f)); c1 *= __expf(fminf(wa.y, 0.f));
                c2 *= __expf(fminf(wb.x, 0.f)); c3 *= __expf(fminf(wb.y, 0.f));
            }
            *(float2*)(C + i0) = make_float2(c0, c1);
            *(float2*)(C + i1) = make_float2(c2, c3);
        }
    }
}

// ======================================================================================
// fused xdd: for all 5 f, xdd_f = x + (x_last-x)*(lambda_f + t1_f @ Blora_f)
// writes w0,g0 fp32 and k0/v0/r0 as bf16 hi/lo. Tile 64m x 64n, K=32.
// ======================================================================================
__global__ void __launch_bounds__(256) xdd_fused(
    const float* __restrict__ t1, const float* __restrict__ Blo5,
    const float* __restrict__ x, const float* __restrict__ xl,
    const float* __restrict__ lam,
    float* __restrict__ w0, float* __restrict__ g0,
    __nv_bfloat16* __restrict__ khi, __nv_bfloat16* __restrict__ klo,
    __nv_bfloat16* __restrict__ vhi, __nv_bfloat16* __restrict__ vlo,
    __nv_bfloat16* __restrict__ rhi, __nv_bfloat16* __restrict__ rlo)
{
    extern __shared__ float sh[];
    float* T1 = sh;              // [5][64][32]
    float* BL = sh + 10240;      // [5][32][64]
    const int tid = threadIdx.x;
    const int bm = blockIdx.y, bn = blockIdx.x;
    const int tx = tid & 15, ty = tid >> 4;

#pragma unroll
    for (int ii = 0; ii < 10; ii++) {
        int c4 = tid + ii * 256;
        int f = c4 >> 9, rem = c4 & 511;
        int row = rem >> 3, kq = rem & 7;
        float4 v = *(const float4*)(t1 + (size_t)f * MROWS * 32 + (size_t)(bm * 64 + row) * 32 + kq * 4);
        *(float4*)&T1[(f * 64 + row) * 32 + kq * 4] = v;
    }
#pragma unroll
    for (int ii = 0; ii < 10; ii++) {
        int c4 = tid + ii * 256;
        int f = c4 >> 9, rem = c4 & 511;
        int k = rem >> 4, cq = rem & 15;
        float4 v = *(const float4*)(Blo5 + (size_t)f * 32 * CDIM + (size_t)k * CDIM + bn * 64 + cq * 4);
        *(float4*)&BL[(f * 32 + k) * 64 + cq * 4] = v;
    }
    __syncthreads();

    float acc[5][4][4];
#pragma unroll
    for (int f = 0; f < 5; f++)
#pragma unroll
        for (int i = 0; i < 4; i++)
#pragma unroll
            for (int j = 0; j < 4; j++) acc[f][i][j] = 0.f;

    for (int k = 0; k < 32; k++) {
#pragma unroll
        for (int f = 0; f < 5; f++) {
            float4 b = *(const float4*)&BL[(f * 32 + k) * 64 + tx * 4];
            float a0 = T1[(f * 64 + ty * 4 + 0) * 32 + k];
            float a1 = T1[(f * 64 + ty * 4 + 1) * 32 + k];
            float a2 = T1[(f * 64 + ty * 4 + 2) * 32 + k];
            float a3 = T1[(f * 64 + ty * 4 + 3) * 32 + k];
            acc[f][0][0] = fmaf(a0, b.x, acc[f][0][0]); acc[f][0][1] = fmaf(a0, b.y, acc[f][0][1]);
            acc[f][0][2] = fmaf(a0, b.z, acc[f][0][2]); acc[f][0][3] = fmaf(a0, b.w, acc[f][0][3]);
            acc[f][1][0] = fmaf(a1, b.x, acc[f][1][0]); acc[f][1][1] = fmaf(a1, b.y, acc[f][1][1]);
            acc[f][1][2] = fmaf(a1, b.z, acc[f][1][2]); acc[f][1][3] = fmaf(a1, b.w, acc[f][1][3]);
            acc[f][2][0] = fmaf(a2, b.x, acc[f][2][0]); acc[f][2][1] = fmaf(a2, b.y, acc[f][2][1]);
            acc[f][2][2] = fmaf(a2, b.z, acc[f][2][2]); acc[f][2][3] = fmaf(a2, b.w, acc[f][2][3]);
            acc[f][3][0] = fmaf(a3, b.x, acc[f][3][0]); acc[f][3][1] = fmaf(a3, b.y, acc[f][3][1]);
            acc[f][3][2] = fmaf(a3, b.z, acc[f][3][2]); acc[f][3][3] = fmaf(a3, b.w, acc[f][3][3]);
        }
    }

    const int n0 = bn * 64 + tx * 4;
    float4 lamv[5];
#pragma unroll
    for (int f = 0; f < 5; f++) lamv[f] = *(const float4*)(lam + f * CDIM + n0);

#pragma unroll
    for (int i = 0; i < 4; i++) {
        const int m = bm * 64 + ty * 4 + i;
        size_t ix = (size_t)m * CDIM + n0;
        float4 xv = *(const float4*)(x + ix);
        float4 xlv = *(const float4*)(xl + ix);
        float4 ba = make_float4(xlv.x - xv.x, xlv.y - xv.y, xlv.z - xv.z, xlv.w - xv.w);
        float4 o[5];
#pragma unroll
        for (int f = 0; f < 5; f++) {
            o[f].x = fmaf(ba.x, lamv[f].x + acc[f][i][0], xv.x);
            o[f].y = fmaf(ba.y, lamv[f].y + acc[f][i][1], xv.y);
            o[f].z = fmaf(ba.z, lamv[f].z + acc[f][i][2], xv.z);
            o[f].w = fmaf(ba.w, lamv[f].w + acc[f][i][3], xv.w);
        }
        *(float4*)(w0 + ix) = o[0];
        *(float4*)(g0 + ix) = o[4];
        uint2 h, l;
        cvt_hilo4(o[1], h, l); *(uint2*)(khi + ix) = h; *(uint2*)(klo + ix) = l;
        cvt_hilo4(o[2], h, l); *(uint2*)(vhi + ix) = h; *(uint2*)(vlo + ix) = l;
        cvt_hilo4(o[3], h, l); *(uint2*)(rhi + ix) = h; *(uint2*)(rlo + ix) = l;
    }
}

// ======================================================================================
// small FFMA GEMM (B normal): C[m,n] = sum_k A[m,k]*B[k,n]
// AOP 1: A = x + (xl - x)*miux[k]. EPI: 0 store; 1 tanh; 2 +=p0[n]; 4 +=p0[n] & dec out
// ======================================================================================
template <int AOP, int EPI>
__global__ void __launch_bounds__(256) sgemm_bn(
    const float* __restrict__ A, const float* __restrict__ B, float* __restrict__ C,
    int M, int N, int K,
    const float* __restrict__ p0, const float* __restrict__ p1, const float* __restrict__ p2,
    float* __restrict__ dout)
{
    __shared__ float As[16][68];
    __shared__ float Bs[16][64];
    const int tid = threadIdx.x;
    const int bm = blockIdx.y, bn = blockIdx.x;
    const int arow = tid >> 2, acol = (tid & 3) << 2;
    const int brow = tid >> 4, bcol = (tid & 15) << 2;
    const int tx = tid & 15, ty = tid >> 4;
    const int gm_a = bm * 64 + arow;
    const int gn_b = bn * 64 + bcol;

    float acc[4][4];
#pragma unroll
    for (int i = 0; i < 4; i++)
#pragma unroll
        for (int j = 0; j < 4; j++) acc[i][j] = 0.f;

    for (int k0 = 0; k0 < K; k0 += 16) {
        float4 a4;
        if (AOP == 0) {
            a4 = *(const float4*)(A + (size_t)gm_a * K + k0 + acol);
        } else {
            float4 xv  = *(const float4*)(p0 + (size_t)gm_a * K + k0 + acol);
            float4 xlv = *(const float4*)(p1 + (size_t)gm_a * K + k0 + acol);
            float4 mv  = *(const float4*)(p2 + k0 + acol);
            a4.x = xv.x + (xlv.x - xv.x) * mv.x;
            a4.y = xv.y + (xlv.y - xv.y) * mv.y;
            a4.z = xv.z + (xlv.z - xv.z) * mv.z;
            a4.w = xv.w + (xlv.w - xv.w) * mv.w;
        }
        As[acol + 0][arow] = a4.x; As[acol + 1][arow] = a4.y;
        As[acol + 2][arow] = a4.z; As[acol + 3][arow] = a4.w;

        float4 b4 = make_float4(0.f, 0.f, 0.f, 0.f);
        if (gn_b < N)
            b4 = *(const float4*)(B + (size_t)(k0 + brow) * N + gn_b);
        Bs[brow][bcol + 0] = b4.x; Bs[brow][bcol + 1] = b4.y;
        Bs[brow][bcol + 2] = b4.z; Bs[brow][bcol + 3] = b4.w;
        __syncthreads();
#pragma unroll
        for (int kk = 0; kk < 16; kk++) {
            float4 a = *(const float4*)&As[kk][ty * 4];
            float4 b = *(const float4*)&Bs[kk][tx * 4];
            acc[0][0] = fmaf(a.x, b.x, acc[0][0]); acc[0][1] = fmaf(a.x, b.y, acc[0][1]);
            acc[0][2] = fmaf(a.x, b.z, acc[0][2]); acc[0][3] = fmaf(a.x, b.w, acc[0][3]);
            acc[1][0] = fmaf(a.y, b.x, acc[1][0]); acc[1][1] = fmaf(a.y, b.y, acc[1][1]);
            acc[1][2] = fmaf(a.y, b.z, acc[1][2]); acc[1][3] = fmaf(a.y, b.w, acc[1][3]);
            acc[2][0] = fmaf(a.z, b.x, acc[2][0]); acc[2][1] = fmaf(a.z, b.y, acc[2][1]);
            acc[2][2] = fmaf(a.z, b.z, acc[2][2]); acc[2][3] = fmaf(a.z, b.w, acc[2][3]);
            acc[3][0] = fmaf(a.w, b.x, acc[3][0]); acc[3][1] = fmaf(a.w, b.y, acc[3][1]);
            acc[3][2] = fmaf(a.w, b.z, acc[3][2]); acc[3][3] = fmaf(a.w, b.w, acc[3][3]);
        }
        __syncthreads();
    }

#pragma unroll
    for (int i = 0; i < 4; i++) {
        int m = bm * 64 + ty * 4 + i;
#pragma unroll
        for (int j = 0; j < 4; j++) {
            int n = bn * 64 + tx * 4 + j;
            if (n >= N) continue;
            float c = acc[i][j];
            size_t ix = (size_t)m * N + n;
            if (EPI == 1) c = tanhf(c);
            else if (EPI == 2) c += p0[n];
            else if (EPI == 4) {
                c += p0[n];
                dout[ix] = __expf(-__expf(c));
            }
            C[ix] = c;
        }
    }
}

// ======================================================================================
// cvec[m,h] = sum_j r[m,h*64+j] * u[h,j] * k[m,h*64+j]   (one warp per (m,h))
// ======================================================================================
__global__ void __launch_bounds__(256) cvec_kernel(
    const float* __restrict__ rb, const float* __restrict__ kb,
    const float* __restrict__ u, float* __restrict__ cv)
{
    int gw = (blockIdx.x * 256 + threadIdx.x) >> 5;
    int lane = threadIdx.x & 31;
    int m = gw >> 4, h = gw & 15;
    size_t base = (size_t)m * CDIM + h * DDIM;
    float p = rb[base + lane] * u[h * DDIM + lane] * kb[base + lane]
            + rb[base + 32 + lane] * u[h * DDIM + 32 + lane] * kb[base + 32 + lane];
#pragma unroll
    for (int o = 16; o > 0; o >>= 1) p += __shfl_xor_sync(0xffffffffu, p, o);
    if (lane == 0) cv[(size_t)m * HNUM + h] = p;
}

// ======================================================================================
// WKV-6 scan (decay + coeff precomputed; double-buffered staging)
// ======================================================================================
__global__ void __launch_bounds__(256) wkv_kernel(
    const float* __restrict__ r, const float* __restrict__ k,
    const float* __restrict__ v, const float* __restrict__ dec,
    const float* __restrict__ cv, const float* __restrict__ s_in,
    float* __restrict__ y, float* __restrict__ s_out)
{
    const int bh = blockIdx.x;
    const int b = bh >> 4, h = bh & 15;
    const int tid = threadIdx.x;
    const int i  = tid & 63;
    const int jg = tid >> 6;
    const int j0 = jg * 16;

    __shared__ float buf[2][4][64];
    __shared__ float cb[2];
    __shared__ float ypart[4][64];

    float st[16];
    size_t sbase = (((size_t)b * HNUM + h) * DDIM + j0) * DDIM + i;
#pragma unroll
    for (int q = 0; q < 16; q++) st[q] = s_in[sbase + (size_t)q * DDIM];

    const int arr = tid >> 6, idx = tid & 63;
    const float* lp = (arr == 0) ? r : (arr == 1) ? k : (arr == 2) ? v : dec;
    const size_t base0 = ((size_t)b * TSEQ) * CDIM + h * DDIM;

    buf[0][arr][idx] = lp[base0 + idx];
    if (tid == 0) cb[0] = cv[(size_t)(b * TSEQ) * HNUM + h];

    for (int t = 0; t < TSEQ; t++) {
        __syncthreads();
        const int cur = t & 1, nxt = cur ^ 1;
        const bool have = (t + 1 < TSEQ);
        float ld = 0.f, cn = 0.f;
        if (have) {
            ld = lp[base0 + (size_t)(t + 1) * CDIM + idx];
            if (tid == 0) cn = cv[(size_t)(b * TSEQ + t + 1) * HNUM + h];
        }

        const float vi = buf[cur][2][i];
        float acc = 0.f;
#pragma unroll
        for (int q = 0; q < 16; q += 4) {
            float4 r4 = *(const float4*)&buf[cur][0][j0 + q];
            float4 k4 = *(const float4*)&buf[cur][1][j0 + q];
            float4 d4 = *(const float4*)&buf[cur][3][j0 + q];
            acc = fmaf(r4.x, st[q + 0], acc); st[q + 0] = fmaf(d4.x, st[q + 0], k4.x * vi);
            acc = fmaf(r4.y, st[q + 1], acc); st[q + 1] = fmaf(d4.y, st[q + 1], k4.y * vi);
            acc = fmaf(r4.z, st[q + 2], acc); st[q + 2] = fmaf(d4.z, st[q + 2], k4.z * vi);
            acc = fmaf(r4.w, st[q + 3], acc); st[q + 3] = fmaf(d4.w, st[q + 3], k4.w * vi);
        }
        ypart[jg][i] = acc;
        if (have) {
            buf[nxt][arr][idx] = ld;
            if (tid == 0) cb[nxt] = cn;
        }
        __syncthreads();

        if (tid < 64) {
            float yv = ypart[0][tid] + ypart[1][tid] + ypart[2][tid] + ypart[3][tid]
                     + buf[cur][2][tid] * cb[cur];
            y[base0 + (size_t)t * CDIM + tid] = yv;
        }
    }

#pragma unroll
    for (int q = 0; q < 16; q++) s_out[sbase + (size_t)q * DDIM] = st[q];
}

// ======================================================================================
// GroupNorm * g -> bf16 hi/lo split output
// ======================================================================================
__global__ void __launch_bounds__(256) gn_kernel(
    const float* __restrict__ y, const float* __restrict__ g,
    const float* __restrict__ gamma, const float* __restrict__ beta,
    __nv_bfloat16* __restrict__ yhi, __nv_bfloat16* __restrict__ ylo)
{
    int warp = (blockIdx.x * blockDim.x + threadIdx.x) >> 5;
    int lane = threadIdx.x & 31;
    int m = warp >> 4, h = warp & 15;
    size_t base = (size_t)m * CDIM + h * DDIM;

    float2 vv = *(const float2*)&y[base + lane * 2];
    float s  = vv.x + vv.y;
    float sq = vv.x * vv.x + vv.y * vv.y;
#pragma unroll
    for (int o = 16; o > 0; o >>= 1) {
        s  += __shfl_xor_sync(0xffffffffu, s,  o);
        sq += __shfl_xor_sync(0xffffffffu, sq, o);
    }
    float mean = s * (1.f / 64.f);
    float var  = sq * (1.f / 64.f) - mean * mean;
    float inv  = rsqrtf(var + 1e-5f * (float)HNUM);

    int c0 = h * DDIM + lane * 2;
    float2 gv = *(const float2*)&g[base + lane * 2];
    float o0 = ((vv.x - mean) * inv * gamma[c0]     + beta[c0])     * gv.x;
    float o1 = ((vv.y - mean) * inv * gamma[c0 + 1] + beta[c0 + 1]) * gv.y;

    __nv_bfloat16 h0 = __float2bfloat16(o0), h1 = __float2bfloat16(o1);
    __nv_bfloat16 l0 = __float2bfloat16(o0 - __bfloat162float(h0));
    __nv_bfloat16 l1 = __float2bfloat16(o1 - __bfloat162float(h1));
    __nv_bfloat162 H = __halves2bfloat162(h0, h1), L = __halves2bfloat162(l0, l1);
    *(uint32_t*)(yhi + base + lane * 2) = *(uint32_t*)&H;
    *(uint32_t*)(ylo + base + lane * 2) = *(uint32_t*)&L;
}

__global__ void __launch_bounds__(256) copy_kernel(
    const float4* __restrict__ src, float4* __restrict__ dst, int n4)
{
    int idx = blockIdx.x * blockDim.x + threadIdx.x;
    if (idx < n4) dst[idx] = src[idx];
}

// ======================================================================================
extern "C" void kernel_launch(void* const* d_in, const int* in_sizes, int n_in,
                              void* d_out, int out_size)
{
    const float* x    = (const float*)d_in[0];
    const float* xlst = (const float*)d_in[1];
    const float* s_in = (const float*)d_in[2];
    const float* miux = (const float*)d_in[3];
    const float* lam  = (const float*)d_in[4];
    const float* Aw   = (const float*)d_in[5];
    const float* Blo5 = (const float*)d_in[6];
    const float* tdm  = (const float*)d_in[7];
    const float* tdA  = (const float*)d_in[8];
    const float* tdB  = (const float*)d_in[9];
    const float* u    = (const float*)d_in[10];
    const float* Wk   = (const float*)d_in[11];
    const float* Wv   = (const float*)d_in[12];
    const float* Wr   = (const float*)d_in[13];
    const float* Wo   = (const float*)d_in[14];
    const float* Wg1  = (const float*)d_in[15];
    const float* Wg2  = (const float*)d_in[16];
    const float* gam  = (const float*)d_in[17];
    const float* bet  = (const float*)d_in[18];
    float* out = (float*)d_out;

    float *t1, *w0, *g0, *h1, *w, *dec, *kb, *vb, *rb, *gb, *yb, *g1, *cv;
    __nv_bfloat16 *khi, *klo, *vhi, *vlo, *rhi, *rlo, *yhi, *ylo, *Whi, *Wlo;
    cudaGetSymbolAddress((void**)&t1,  g_t1);
    cudaGetSymbolAddress((void**)&w0,  g_w0);
    cudaGetSymbolAddress((void**)&g0,  g_g0);
    cudaGetSymbolAddress((void**)&khi, g_khi); cudaGetSymbolAddress((void**)&klo, g_klo);
    cudaGetSymbolAddress((void**)&vhi, g_vhi); cudaGetSymbolAddress((void**)&vlo, g_vlo);
    cudaGetSymbolAddress((void**)&rhi, g_rhi); cudaGetSymbolAddress((void**)&rlo, g_rlo);
    cudaGetSymbolAddress((void**)&yhi, g_yhi); cudaGetSymbolAddress((void**)&ylo, g_ylo);
    cudaGetSymbolAddress((void**)&Whi, g_Whi); cudaGetSymbolAddress((void**)&Wlo, g_Wlo);
    cudaGetSymbolAddress((void**)&h1,  g_h1);
    cudaGetSymbolAddress((void**)&w,   g_w);
    cudaGetSymbolAddress((void**)&dec, g_dec);
    cudaGetSymbolAddress((void**)&kb,  g_kb);
    cudaGetSymbolAddress((void**)&vb,  g_vb);
    cudaGetSymbolAddress((void**)&rb,  g_rb);
    cudaGetSymbolAddress((void**)&gb,  g_gb);
    cudaGetSymbolAddress((void**)&yb,  g_yb);
    cudaGetSymbolAddress((void**)&g1,  g_g1);
    cudaGetSymbolAddress((void**)&cv,  g_cv);

    const size_t WSZ = (size_t)CDIM * CDIM;
    cudaFuncSetAttribute(mma_gemm16<0>, cudaFuncAttributeMaxDynamicSharedMemorySize, 3 * STGB);
    cudaFuncSetAttribute(mma_gemm16<1>, cudaFuncAttributeMaxDynamicSharedMemorySize, 3 * STGB);
    cudaFuncSetAttribute(xdd_fused, cudaFuncAttributeMaxDynamicSharedMemorySize, 81920);

    const size_t MC = (size_t)MROWS * CDIM;
    dim3 thr(256);
    dim3 mmaGrid(CDIM / 256, MROWS / 128);

    // 0) split weights to bf16 hi/lo
    const int wn4 = (int)(WSZ / 4);
    split_kernel<<<(wn4 + 255) / 256, thr>>>((const float4*)Wk, Whi + 0 * WSZ, Wlo + 0 * WSZ, wn4);
    split_kernel<<<(wn4 + 255) / 256, thr>>>((const float4*)Wv, Whi + 1 * WSZ, Wlo + 1 * WSZ, wn4);
    split_kernel<<<(wn4 + 255) / 256, thr>>>((const float4*)Wr, Whi + 2 * WSZ, Wlo + 2 * WSZ, wn4);
    split_kernel<<<(wn4 + 255) / 256, thr>>>((const float4*)Wo, Whi + 3 * WSZ, Wlo + 3 * WSZ, wn4);

    // 1) t1 = tanh(xl @ A)
    sgemm_bn<1, 1><<<dim3(3, MROWS / 64), thr>>>(x, Aw, t1, MROWS, 160, CDIM, x, xlst, miux, nullptr);

    // 2) fused xdd -> w0, g0 fp32; k/v/r bf16 hi/lo
    xdd_fused<<<dim3(CDIM / 64, MROWS / 64), thr, 81920>>>(
        t1, Blo5, x, xlst, lam, w0, g0, khi, klo, vhi, vlo, rhi, rlo);

    // 3) h1 = tanh(w0 @ td_A)
    sgemm_bn<0, 1><<<dim3(1, MROWS / 64), thr>>>(w0, tdA, h1, MROWS, 64, CDIM, nullptr, nullptr, nullptr, nullptr);
    // 4) w = tdm + h1 @ td_B ; dec = exp(-exp(w))
    sgemm_bn<0, 4><<<dim3(CDIM / 64, MROWS / 64), thr>>>(h1, tdB, w, MROWS, CDIM, 64, tdm, nullptr, nullptr, dec);

    // 5-7) big projections (bf16x3, cp.async pipelined HMMA)
    mma_gemm16<1><<<mmaGrid, thr, 3 * STGB>>>(khi, klo, Whi + 0 * WSZ, Wlo + 0 * WSZ, kb, w);
    mma_gemm16<0><<<mmaGrid, thr, 3 * STGB>>>(vhi, vlo, Whi + 1 * WSZ, Wlo + 1 * WSZ, vb, nullptr);
    mma_gemm16<0><<<mmaGrid, thr, 3 * STGB>>>(rhi, rlo, Whi + 2 * WSZ, Wlo + 2 * WSZ, rb, nullptr);

    // 8-9) gate
    sgemm_bn<0, 1><<<dim3(3, MROWS / 64), thr>>>(g0, Wg1, g1, MROWS, 160, CDIM, nullptr, nullptr, nullptr, nullptr);
    sgemm_bn<0, 0><<<dim3(CDIM / 64, MROWS / 64), thr>>>(g1, Wg2, gb, MROWS, CDIM, 160, nullptr, nullptr, nullptr, nullptr);

    // 10) cvec precompute
    cvec_kernel<<<(MROWS * HNUM) / 8, thr>>>(rb, kb, u, cv);

    // 11) WKV-6 scan
    wkv_kernel<<<BSZ * HNUM, thr>>>(rb, kb, vb, dec, cv, s_in, yb, out + 2 * MC);

    // 12) GroupNorm * g -> bf16 hi/lo
    gn_kernel<<<(MROWS * HNUM) / 8, thr>>>(yb, gb, gam, bet, yhi, ylo);

    // 13) out = (yn*g) @ Wo^T
    mma_gemm16<0><<<mmaGrid, thr, 3 * STGB>>>(yhi, ylo, Whi + 3 * WSZ, Wlo + 3 * WSZ, out, nullptr);

    // 14) x_raw passthrough
    copy_kernel<<<(int)(MC / 4 / 256), thr>>>((const float4*)x, (float4*)(out + MC), (int)(MC / 4));
}

// round 5
// speedup vs baseline: 1.8778x; 1.1414x over previous
#include <cuda_runtime.h>
#include <cuda_bf16.h>
#include <stdint.h>
#include <math.h>

#define MROWS 16384   // B*T = 8*2048
#define CDIM  1024
#define HNUM  16
#define DDIM  64
#define TSEQ  2048
#define BSZ   8

// ---------------- scratch (static device memory; no runtime allocation) ----------------
__device__ float g_t1 [(size_t)MROWS * 160];
__device__ float g_w0 [(size_t)MROWS * CDIM];
__device__ __nv_bfloat16 g_xlhi[(size_t)MROWS * CDIM], g_xllo[(size_t)MROWS * CDIM];
__device__ __nv_bfloat16 g_g0hi[(size_t)MROWS * CDIM], g_g0lo[(size_t)MROWS * CDIM];
__device__ __nv_bfloat16 g_g1hi[(size_t)MROWS * 160],  g_g1lo[(size_t)MROWS * 160];
__device__ __nv_bfloat16 g_khi[(size_t)MROWS * CDIM], g_klo[(size_t)MROWS * CDIM];
__device__ __nv_bfloat16 g_vhi[(size_t)MROWS * CDIM], g_vlo[(size_t)MROWS * CDIM];
__device__ __nv_bfloat16 g_rhi[(size_t)MROWS * CDIM], g_rlo[(size_t)MROWS * CDIM];
__device__ __nv_bfloat16 g_yhi[(size_t)MROWS * CDIM], g_ylo[(size_t)MROWS * CDIM];
__device__ __nv_bfloat16 g_Whi[4][(size_t)CDIM * CDIM], g_Wlo[4][(size_t)CDIM * CDIM];
__device__ __nv_bfloat16 g_Athi[(size_t)256 * CDIM], g_Atlo[(size_t)256 * CDIM];
__device__ __nv_bfloat16 g_G1thi[(size_t)256 * CDIM], g_G1tlo[(size_t)256 * CDIM];
__device__ __nv_bfloat16 g_G2thi[(size_t)CDIM * 160], g_G2tlo[(size_t)CDIM * 160];
__device__ float g_h1 [(size_t)MROWS * 64];
__device__ float g_w  [(size_t)MROWS * CDIM];
__device__ float g_dec[(size_t)MROWS * CDIM];
__device__ float g_kb [(size_t)MROWS * CDIM];
__device__ float g_vb [(size_t)MROWS * CDIM];
__device__ float g_rb [(size_t)MROWS * CDIM];
__device__ float g_gb [(size_t)MROWS * CDIM];
__device__ float g_yb [(size_t)MROWS * CDIM];
__device__ float g_cv [(size_t)MROWS * HNUM];

// ======================================================================================
// helpers
// ======================================================================================
__device__ __forceinline__ uint32_t smem_u32(const void* p) {
    uint32_t a;
    asm("{ .reg .u64 t; cvta.to.shared.u64 t, %1; cvt.u32.u64 %0, t; }" : "=r"(a) : "l"(p));
    return a;
}
__device__ __forceinline__ void ldsm4(uint32_t* r, uint32_t addr) {
    asm volatile("ldmatrix.sync.aligned.m8n8.x4.shared.b16 {%0,%1,%2,%3}, [%4];"
        : "=r"(r[0]), "=r"(r[1]), "=r"(r[2]), "=r"(r[3]) : "r"(addr));
}
__device__ __forceinline__ void mma16816(float* c, const uint32_t* a, const uint32_t* b) {
    asm volatile("mma.sync.aligned.m16n8k16.row.col.f32.bf16.bf16.f32 "
        "{%0,%1,%2,%3}, {%4,%5,%6,%7}, {%8,%9}, {%0,%1,%2,%3};"
        : "+f"(c[0]), "+f"(c[1]), "+f"(c[2]), "+f"(c[3])
        : "r"(a[0]), "r"(a[1]), "r"(a[2]), "r"(a[3]), "r"(b[0]), "r"(b[1]));
}
#define CP16(d, s) asm volatile("cp.async.cg.shared.global [%0], [%1], 16;" :: "r"(d), "l"(s))
#define CPCOMMIT() asm volatile("cp.async.commit_group;" ::: "memory")
#define CPWAIT1()  asm volatile("cp.async.wait_group 1;" ::: "memory")

__device__ __forceinline__ void cvt_hilo4(float4 v, uint2& hi, uint2& lo) {
    __nv_bfloat16 h0 = __float2bfloat16(v.x), h1 = __float2bfloat16(v.y);
    __nv_bfloat16 h2 = __float2bfloat16(v.z), h3 = __float2bfloat16(v.w);
    __nv_bfloat16 l0 = __float2bfloat16(v.x - __bfloat162float(h0));
    __nv_bfloat16 l1 = __float2bfloat16(v.y - __bfloat162float(h1));
    __nv_bfloat16 l2 = __float2bfloat16(v.z - __bfloat162float(h2));
    __nv_bfloat16 l3 = __float2bfloat16(v.w - __bfloat162float(h3));
    __nv_bfloat162 H01 = __halves2bfloat162(h0, h1), H23 = __halves2bfloat162(h2, h3);
    __nv_bfloat162 L01 = __halves2bfloat162(l0, l1), L23 = __halves2bfloat162(l2, l3);
    hi = make_uint2(*(uint32_t*)&H01, *(uint32_t*)&H23);
    lo = make_uint2(*(uint32_t*)&L01, *(uint32_t*)&L23);
}

// ======================================================================================
// prep kernels
// ======================================================================================
__global__ void __launch_bounds__(256) split_kernel(
    const float4* __restrict__ src, __nv_bfloat16* __restrict__ hi,
    __nv_bfloat16* __restrict__ lo, int n4)
{
    int idx = blockIdx.x * 256 + threadIdx.x;
    if (idx >= n4) return;
    uint2 h, l;
    cvt_hilo4(src[idx], h, l);
    *(uint2*)(hi + (size_t)idx * 4) = h;
    *(uint2*)(lo + (size_t)idx * 4) = l;
}

// transpose + zero-pad + split: in (K x N) -> out (Npad x K), out[n,k]=in[k,n]
__global__ void __launch_bounds__(256) tpad_split(
    const float* __restrict__ in, __nv_bfloat16* __restrict__ ohi,
    __nv_bfloat16* __restrict__ olo, int K, int N, int Npad)
{
    int t = blockIdx.x * 256 + threadIdx.x;
    if (t >= Npad * K) return;
    int n = t / K, k = t - n * K;
    float v = (n < N) ? in[(size_t)k * N + n] : 0.f;
    __nv_bfloat16 h = __float2bfloat16(v);
    __nv_bfloat16 l = __float2bfloat16(v - __bfloat162float(h));
    ohi[t] = h; olo[t] = l;
}

// xl = x + (x_last - x)*miu_x -> bf16 hi/lo ; also x_raw passthrough
__global__ void __launch_bounds__(256) xprep_kernel(
    const float4* __restrict__ x, const float4* __restrict__ xl,
    const float* __restrict__ miux,
    __nv_bfloat16* __restrict__ xhi, __nv_bfloat16* __restrict__ xlo,
    float4* __restrict__ xraw)
{
    int idx = blockIdx.x * 256 + threadIdx.x;   // MC/4 total
    float4 xv = x[idx], xlv = xl[idx];
    float4 mv = *(const float4*)(miux + (idx & 255) * 4);
    float4 o;
    o.x = fmaf(xlv.x - xv.x, mv.x, xv.x);
    o.y = fmaf(xlv.y - xv.y, mv.y, xv.y);
    o.z = fmaf(xlv.z - xv.z, mv.z, xv.z);
    o.w = fmaf(xlv.w - xv.w, mv.w, xv.w);
    uint2 h, l;
    cvt_hilo4(o, h, l);
    *(uint2*)(xhi + (size_t)idx * 4) = h;
    *(uint2*)(xlo + (size_t)idx * 4) = l;
    xraw[idx] = xv;
}

// ======================================================================================
// bf16x3 HMMA GEMM, cp.async 3-stage pipeline. C[m,n] = sum_k A[m,k]*B[n,k].
// Tile 128m x 256n, BK=32, KCH chunks (K = KCH*32), row stride kst for A and B.
// EPI 0: fp32 store stride CDIM, optional *exp(min(w,0)) when wptr != null (z-batched)
// EPI 2: tanh -> fp32 store stride 160, n<160 only
// EPI 3: tanh -> bf16 hi/lo store stride 160, n<160 only
// ======================================================================================
#define GP    40
#define STGB  61440
#define OALO  10240
#define OBHI  20480
#define OBLO  40960

struct GemmSet {
    const __nv_bfloat16 *ahi, *alo, *bhi, *blo;
    float* c;
    const float* wptr;
};
struct GemmBatch { GemmSet s[3]; };

template <int EPI, int KCH>
__global__ void __launch_bounds__(256, 1) mma_gemm16(
    GemmBatch gbat, int kst,
    __nv_bfloat16* __restrict__ chi, __nv_bfloat16* __restrict__ clo)
{
    const GemmSet gs = gbat.s[blockIdx.z];
    extern __shared__ char smem[];
    const int tid = threadIdx.x, wid = tid >> 5, lane = tid & 31;
    const int bm = blockIdx.y, bn = blockIdx.x;
    const uint32_t sbase = smem_u32(smem);

    const int q = tid & 3, r0 = tid >> 2;
    const __nv_bfloat16* pAhi = gs.ahi + (size_t)(bm * 128 + r0) * kst + q * 8;
    const __nv_bfloat16* pAlo = gs.alo + (size_t)(bm * 128 + r0) * kst + q * 8;
    const __nv_bfloat16* pBhi = gs.bhi + (size_t)(bn * 256 + r0) * kst + q * 8;
    const __nv_bfloat16* pBlo = gs.blo + (size_t)(bn * 256 + r0) * kst + q * 8;
    const uint32_t dA = (uint32_t)(r0 * 80 + q * 16);
    const size_t kst64 = (size_t)64 * kst;

    auto issue = [&](int s, int k0) {
        uint32_t sb2 = sbase + s * STGB;
        CP16(sb2 + dA,               pAhi + k0);
        CP16(sb2 + dA + 5120,        pAhi + k0 + kst64);
        CP16(sb2 + OALO + dA,        pAlo + k0);
        CP16(sb2 + OALO + dA + 5120, pAlo + k0 + kst64);
#pragma unroll
        for (int i = 0; i < 4; i++) {
            CP16(sb2 + OBHI + dA + i * 5120, pBhi + k0 + i * kst64);
            CP16(sb2 + OBLO + dA + i * 5120, pBlo + k0 + i * kst64);
        }
    };

    float acc[2][16][4];
#pragma unroll
    for (int a = 0; a < 2; a++)
#pragma unroll
        for (int b = 0; b < 16; b++)
#pragma unroll
            for (int c = 0; c < 4; c++) acc[a][b][c] = 0.f;

    const int arow = (wid & 3) * 32 + (lane & 7) + ((lane >> 3) & 1) * 8;
    const int acol8 = (lane >> 4) * 8;
    const int brow = (wid >> 2) * 128 + ((lane >> 4) << 3) + (lane & 7);
    const int bcol8 = ((lane >> 3) & 1) * 8;

    issue(0, 0);  CPCOMMIT();
    if (KCH > 1) issue(1, 32);
    CPCOMMIT();

    for (int c = 0; c < KCH; c++) {
        CPWAIT1();
        __syncthreads();
        {
            int cn = c + 2;
            if (cn < KCH) issue(cn % 3, cn * 32);
            CPCOMMIT();
        }
        const uint32_t sA = sbase + (c % 3) * STGB;
#pragma unroll
        for (int ks = 0; ks < 2; ks++) {
            const int kc = ks * 16;
            uint32_t ah[2][4], al[2][4];
#pragma unroll
            for (int mt = 0; mt < 2; mt++) {
                uint32_t off = (uint32_t)((arow + mt * 16) * GP + kc + acol8) * 2;
                ldsm4(ah[mt], sA + off);
                ldsm4(al[mt], sA + OALO + off);
            }
#pragma unroll
            for (int nt2 = 0; nt2 < 8; nt2++) {
                uint32_t boff = (uint32_t)((brow + nt2 * 16) * GP + kc + bcol8) * 2;
                uint32_t rh[4], rl[4];
                ldsm4(rh, sA + OBHI + boff);
                ldsm4(rl, sA + OBLO + boff);
#pragma unroll
                for (int mt = 0; mt < 2; mt++) {
                    mma16816(acc[mt][nt2 * 2], ah[mt], rh);
                    mma16816(acc[mt][nt2 * 2], ah[mt], rl);
                    mma16816(acc[mt][nt2 * 2], al[mt], rh);
                    mma16816(acc[mt][nt2 * 2 + 1], ah[mt], rh + 2);
                    mma16816(acc[mt][nt2 * 2 + 1], ah[mt], rl + 2);
                    mma16816(acc[mt][nt2 * 2 + 1], al[mt], rh + 2);
                }
            }
        }
    }

    // epilogue
#pragma unroll
    for (int mt = 0; mt < 2; mt++) {
        const int m = bm * 128 + (wid & 3) * 32 + mt * 16 + (lane >> 2);
#pragma unroll
        for (int nt = 0; nt < 16; nt++) {
            const int n = bn * 256 + (wid >> 2) * 128 + nt * 8 + (lane & 3) * 2;
            float c0 = acc[mt][nt][0], c1 = acc[mt][nt][1];
            float c2 = acc[mt][nt][2], c3 = acc[mt][nt][3];
            if (EPI == 0) {
                size_t i0 = (size_t)m * CDIM + n;
                size_t i1 = i0 + (size_t)8 * CDIM;
                if (gs.wptr) {
                    float2 wa = *(const float2*)(gs.wptr + i0);
                    float2 wb = *(const float2*)(gs.wptr + i1);
                    c0 *= __expf(fminf(wa.x, 0.f)); c1 *= __expf(fminf(wa.y, 0.f));
                    c2 *= __expf(fminf(wb.x, 0.f)); c3 *= __expf(fminf(wb.y, 0.f));
                }
                *(float2*)(gs.c + i0) = make_float2(c0, c1);
                *(float2*)(gs.c + i1) = make_float2(c2, c3);
            } else {
                if (n >= 160) continue;
                c0 = tanhf(c0); c1 = tanhf(c1); c2 = tanhf(c2); c3 = tanhf(c3);
                size_t i0 = (size_t)m * 160 + n;
                size_t i1 = i0 + (size_t)8 * 160;
                if (EPI == 2) {
                    *(float2*)(gs.c + i0) = make_float2(c0, c1);
                    *(float2*)(gs.c + i1) = make_float2(c2, c3);
                } else {
                    __nv_bfloat16 h0 = __float2bfloat16(c0), h1 = __float2bfloat16(c1);
                    __nv_bfloat16 h2 = __float2bfloat16(c2), h3 = __float2bfloat16(c3);
                    __nv_bfloat16 l0 = __float2bfloat16(c0 - __bfloat162float(h0));
                    __nv_bfloat16 l1 = __float2bfloat16(c1 - __bfloat162float(h1));
                    __nv_bfloat16 l2 = __float2bfloat16(c2 - __bfloat162float(h2));
                    __nv_bfloat16 l3 = __float2bfloat16(c3 - __bfloat162float(h3));
                    __nv_bfloat162 H01 = __halves2bfloat162(h0, h1), H23 = __halves2bfloat162(h2, h3);
                    __nv_bfloat162 L01 = __halves2bfloat162(l0, l1), L23 = __halves2bfloat162(l2, l3);
                    *(uint32_t*)(chi + i0) = *(uint32_t*)&H01;
                    *(uint32_t*)(chi + i1) = *(uint32_t*)&H23;
                    *(uint32_t*)(clo + i0) = *(uint32_t*)&L01;
                    *(uint32_t*)(clo + i1) = *(uint32_t*)&L23;
                }
            }
        }
    }
}

// ======================================================================================
// fused xdd (K=32 LoRA): w0 fp32; g0/k0/v0/r0 -> bf16 hi/lo
// ======================================================================================
__global__ void __launch_bounds__(256) xdd_fused(
    const float* __restrict__ t1, const float* __restrict__ Blo5,
    const float* __restrict__ x, const float* __restrict__ xl,
    const float* __restrict__ lam,
    float* __restrict__ w0,
    __nv_bfloat16* __restrict__ g0hi, __nv_bfloat16* __restrict__ g0lo,
    __nv_bfloat16* __restrict__ khi, __nv_bfloat16* __restrict__ klo,
    __nv_bfloat16* __restrict__ vhi, __nv_bfloat16* __restrict__ vlo,
    __nv_bfloat16* __restrict__ rhi, __nv_bfloat16* __restrict__ rlo)
{
    extern __shared__ float sh[];
    float* T1 = sh;              // [5][64][32]
    float* BL = sh + 10240;      // [5][32][64]
    const int tid = threadIdx.x;
    const int bm = blockIdx.y, bn = blockIdx.x;
    const int tx = tid & 15, ty = tid >> 4;

#pragma unroll
    for (int ii = 0; ii < 10; ii++) {
        int c4 = tid + ii * 256;
        int f = c4 >> 9, rem = c4 & 511;
        int row = rem >> 3, kq = rem & 7;
        float4 v = *(const float4*)(t1 + (size_t)f * MROWS * 32 + (size_t)(bm * 64 + row) * 32 + kq * 4);
        *(float4*)&T1[(f * 64 + row) * 32 + kq * 4] = v;
    }
#pragma unroll
    for (int ii = 0; ii < 10; ii++) {
        int c4 = tid + ii * 256;
        int f = c4 >> 9, rem = c4 & 511;
        int k = rem >> 4, cq = rem & 15;
        float4 v = *(const float4*)(Blo5 + (size_t)f * 32 * CDIM + (size_t)k * CDIM + bn * 64 + cq * 4);
        *(float4*)&BL[(f * 32 + k) * 64 + cq * 4] = v;
    }
    __syncthreads();

    float acc[5][4][4];
#pragma unroll
    for (int f = 0; f < 5; f++)
#pragma unroll
        for (int i = 0; i < 4; i++)
#pragma unroll
            for (int j = 0; j < 4; j++) acc[f][i][j] = 0.f;

    for (int k = 0; k < 32; k++) {
#pragma unroll
        for (int f = 0; f < 5; f++) {
            float4 b = *(const float4*)&BL[(f * 32 + k) * 64 + tx * 4];
            float a0 = T1[(f * 64 + ty * 4 + 0) * 32 + k];
            float a1 = T1[(f * 64 + ty * 4 + 1) * 32 + k];
            float a2 = T1[(f * 64 + ty * 4 + 2) * 32 + k];
            float a3 = T1[(f * 64 + ty * 4 + 3) * 32 + k];
            acc[f][0][0] = fmaf(a0, b.x, acc[f][0][0]); acc[f][0][1] = fmaf(a0, b.y, acc[f][0][1]);
            acc[f][0][2] = fmaf(a0, b.z, acc[f][0][2]); acc[f][0][3] = fmaf(a0, b.w, acc[f][0][3]);
            acc[f][1][0] = fmaf(a1, b.x, acc[f][1][0]); acc[f][1][1] = fmaf(a1, b.y, acc[f][1][1]);
            acc[f][1][2] = fmaf(a1, b.z, acc[f][1][2]); acc[f][1][3] = fmaf(a1, b.w, acc[f][1][3]);
            acc[f][2][0] = fmaf(a2, b.x, acc[f][2][0]); acc[f][2][1] = fmaf(a2, b.y, acc[f][2][1]);
            acc[f][2][2] = fmaf(a2, b.z, acc[f][2][2]); acc[f][2][3] = fmaf(a2, b.w, acc[f][2][3]);
            acc[f][3][0] = fmaf(a3, b.x, acc[f][3][0]); acc[f][3][1] = fmaf(a3, b.y, acc[f][3][1]);
            acc[f][3][2] = fmaf(a3, b.z, acc[f][3][2]); acc[f][3][3] = fmaf(a3, b.w, acc[f][3][3]);
        }
    }

    const int n0 = bn * 64 + tx * 4;
    float4 lamv[5];
#pragma unroll
    for (int f = 0; f < 5; f++) lamv[f] = *(const float4*)(lam + f * CDIM + n0);

#pragma unroll
    for (int i = 0; i < 4; i++) {
        const int m = bm * 64 + ty * 4 + i;
        size_t ix = (size_t)m * CDIM + n0;
        float4 xv = *(const float4*)(x + ix);
        float4 xlv = *(const float4*)(xl + ix);
        float4 ba = make_float4(xlv.x - xv.x, xlv.y - xv.y, xlv.z - xv.z, xlv.w - xv.w);
        float4 o[5];
#pragma unroll
        for (int f = 0; f < 5; f++) {
            o[f].x = fmaf(ba.x, lamv[f].x + acc[f][i][0], xv.x);
            o[f].y = fmaf(ba.y, lamv[f].y + acc[f][i][1], xv.y);
            o[f].z = fmaf(ba.z, lamv[f].z + acc[f][i][2], xv.z);
            o[f].w = fmaf(ba.w, lamv[f].w + acc[f][i][3], xv.w);
        }
        *(float4*)(w0 + ix) = o[0];
        uint2 h, l;
        cvt_hilo4(o[1], h, l); *(uint2*)(khi + ix) = h; *(uint2*)(klo + ix) = l;
        cvt_hilo4(o[2], h, l); *(uint2*)(vhi + ix) = h; *(uint2*)(vlo + ix) = l;
        cvt_hilo4(o[3], h, l); *(uint2*)(rhi + ix) = h; *(uint2*)(rlo + ix) = l;
        cvt_hilo4(o[4], h, l); *(uint2*)(g0hi + ix) = h; *(uint2*)(g0lo + ix) = l;
    }
}

// ======================================================================================
// small FFMA GEMM (B normal). EPI: 1 tanh; 4 +=p0[n] & dec=exp(-exp(c))
// ======================================================================================
template <int EPI>
__global__ void __launch_bounds__(256) sgemm_bn(
    const float* __restrict__ A, const float* __restrict__ B, float* __restrict__ C,
    int M, int N, int K, const float* __restrict__ p0, float* __restrict__ dout)
{
    __shared__ float As[16][68];
    __shared__ float Bs[16][64];
    const int tid = threadIdx.x;
    const int bm = blockIdx.y, bn = blockIdx.x;
    const int arow = tid >> 2, acol = (tid & 3) << 2;
    const int brow = tid >> 4, bcol = (tid & 15) << 2;
    const int tx = tid & 15, ty = tid >> 4;
    const int gm_a = bm * 64 + arow;
    const int gn_b = bn * 64 + bcol;

    float acc[4][4];
#pragma unroll
    for (int i = 0; i < 4; i++)
#pragma unroll
        for (int j = 0; j < 4; j++) acc[i][j] = 0.f;

    for (int k0 = 0; k0 < K; k0 += 16) {
        float4 a4 = *(const float4*)(A + (size_t)gm_a * K + k0 + acol);
        As[acol + 0][arow] = a4.x; As[acol + 1][arow] = a4.y;
        As[acol + 2][arow] = a4.z; As[acol + 3][arow] = a4.w;

        float4 b4 = make_float4(0.f, 0.f, 0.f, 0.f);
        if (gn_b < N)
            b4 = *(const float4*)(B + (size_t)(k0 + brow) * N + gn_b);
        Bs[brow][bcol + 0] = b4.x; Bs[brow][bcol + 1] = b4.y;
        Bs[brow][bcol + 2] = b4.z; Bs[brow][bcol + 3] = b4.w;
        __syncthreads();
#pragma unroll
        for (int kk = 0; kk < 16; kk++) {
            float4 a = *(const float4*)&As[kk][ty * 4];
            float4 b = *(const float4*)&Bs[kk][tx * 4];
            acc[0][0] = fmaf(a.x, b.x, acc[0][0]); acc[0][1] = fmaf(a.x, b.y, acc[0][1]);
            acc[0][2] = fmaf(a.x, b.z, acc[0][2]); acc[0][3] = fmaf(a.x, b.w, acc[0][3]);
            acc[1][0] = fmaf(a.y, b.x, acc[1][0]); acc[1][1] = fmaf(a.y, b.y, acc[1][1]);
            acc[1][2] = fmaf(a.y, b.z, acc[1][2]); acc[1][3] = fmaf(a.y, b.w, acc[1][3]);
            acc[2][0] = fmaf(a.z, b.x, acc[2][0]); acc[2][1] = fmaf(a.z, b.y, acc[2][1]);
            acc[2][2] = fmaf(a.z, b.z, acc[2][2]); acc[2][3] = fmaf(a.z, b.w, acc[2][3]);
            acc[3][0] = fmaf(a.w, b.x, acc[3][0]); acc[3][1] = fmaf(a.w, b.y, acc[3][1]);
            acc[3][2] = fmaf(a.w, b.z, acc[3][2]); acc[3][3] = fmaf(a.w, b.w, acc[3][3]);
        }
        __syncthreads();
    }

#pragma unroll
    for (int i = 0; i < 4; i++) {
        int m = bm * 64 + ty * 4 + i;
#pragma unroll
        for (int j = 0; j < 4; j++) {
            int n = bn * 64 + tx * 4 + j;
            if (n >= N) continue;
            float c = acc[i][j];
            size_t ix = (size_t)m * N + n;
            if (EPI == 1) c = tanhf(c);
            else if (EPI == 4) {
                c += p0[n];
                dout[ix] = __expf(-__expf(c));
            }
            C[ix] = c;
        }
    }
}

// ======================================================================================
// cvec[m,h] = sum_j r*u*k
// ======================================================================================
__global__ void __launch_bounds__(256) cvec_kernel(
    const float* __restrict__ rb, const float* __restrict__ kb,
    const float* __restrict__ u, float* __restrict__ cv)
{
    int gw = (blockIdx.x * 256 + threadIdx.x) >> 5;
    int lane = threadIdx.x & 31;
    int m = gw >> 4, h = gw & 15;
    size_t base = (size_t)m * CDIM + h * DDIM;
    float p = rb[base + lane] * u[h * DDIM + lane] * kb[base + lane]
            + rb[base + 32 + lane] * u[h * DDIM + 32 + lane] * kb[base + 32 + lane];
#pragma unroll
    for (int o = 16; o > 0; o >>= 1) p += __shfl_xor_sync(0xffffffffu, p, o);
    if (lane == 0) cv[(size_t)m * HNUM + h] = p;
}

// ======================================================================================
// WKV-6 scan — single __syncthreads per step
// ======================================================================================
__global__ void __launch_bounds__(256) wkv_kernel(
    const float* __restrict__ r, const float* __restrict__ k,
    const float* __restrict__ v, const float* __restrict__ dec,
    const float* __restrict__ cv, const float* __restrict__ s_in,
    float* __restrict__ y, float* __restrict__ s_out)
{
    const int bh = blockIdx.x;
    const int b = bh >> 4, h = bh & 15;
    const int tid = threadIdx.x;
    const int i  = tid & 63;
    const int jg = tid >> 6;
    const int j0 = jg * 16;

    __shared__ float buf[2][4][64];
    __shared__ float ypart[2][4][64];
    __shared__ float cb[2];

    float st[16];
    size_t sbase = (((size_t)b * HNUM + h) * DDIM + j0) * DDIM + i;
#pragma unroll
    for (int q = 0; q < 16; q++) st[q] = s_in[sbase + (size_t)q * DDIM];

    const int arr = tid >> 6, idx = tid & 63;
    const float* lp = (arr == 0) ? r : (arr == 1) ? k : (arr == 2) ? v : dec;
    const size_t base0 = ((size_t)b * TSEQ) * CDIM + h * DDIM;

    buf[0][arr][idx] = lp[base0 + idx];
    if (tid == 0) cb[0] = cv[(size_t)(b * TSEQ) * HNUM + h];
    float ld = (TSEQ > 1) ? lp[base0 + CDIM + idx] : 0.f;
    float cn = 0.f;
    if (tid == 0 && TSEQ > 1) cn = cv[(size_t)(b * TSEQ + 1) * HNUM + h];
    __syncthreads();

    for (int t = 0; t < TSEQ; t++) {
        const int cur = t & 1, nxt = cur ^ 1;

        const float vi = buf[cur][2][i];
        float acc = 0.f;
#pragma unroll
        for (int q = 0; q < 16; q += 4) {
            float4 r4 = *(const float4*)&buf[cur][0][j0 + q];
            float4 k4 = *(const float4*)&buf[cur][1][j0 + q];
            float4 d4 = *(const float4*)&buf[cur][3][j0 + q];
            acc = fmaf(r4.x, st[q + 0], acc); st[q + 0] = fmaf(d4.x, st[q + 0], k4.x * vi);
            acc = fmaf(r4.y, st[q + 1], acc); st[q + 1] = fmaf(d4.y, st[q + 1], k4.y * vi);
            acc = fmaf(r4.z, st[q + 2], acc); st[q + 2] = fmaf(d4.z, st[q + 2], k4.z * vi);
            acc = fmaf(r4.w, st[q + 3], acc); st[q + 3] = fmaf(d4.w, st[q + 3], k4.w * vi);
        }
        ypart[cur][jg][i] = acc;

        float vcur = 0.f, ccur = 0.f;
        if (tid < 64) { vcur = buf[cur][2][tid]; ccur = cb[cur]; }
        if (t + 1 < TSEQ) {
            buf[nxt][arr][idx] = ld;
            if (tid == 0) cb[nxt] = cn;
        }
        __syncthreads();

        if (t + 2 < TSEQ) {
            ld = lp[base0 + (size_t)(t + 2) * CDIM + idx];
            if (tid == 0) cn = cv[(size_t)(b * TSEQ + t + 2) * HNUM + h];
        }
        if (tid < 64) {
            float yv = ypart[cur][0][tid] + ypart[cur][1][tid] + ypart[cur][2][tid]
                     + ypart[cur][3][tid] + vcur * ccur;
            y[base0 + (size_t)t * CDIM + tid] = yv;
        }
    }

#pragma unroll
    for (int q = 0; q < 16; q++) s_out[sbase + (size_t)q * DDIM] = st[q];
}

// ======================================================================================
// GroupNorm * g -> bf16 hi/lo
// ======================================================================================
__global__ void __launch_bounds__(256) gn_kernel(
    const float* __restrict__ y, const float* __restrict__ g,
    const float* __restrict__ gamma, const float* __restrict__ beta,
    __nv_bfloat16* __restrict__ yhi, __nv_bfloat16* __restrict__ ylo)
{
    int warp = (blockIdx.x * blockDim.x + threadIdx.x) >> 5;
    int lane = threadIdx.x & 31;
    int m = warp >> 4, h = warp & 15;
    size_t base = (size_t)m * CDIM + h * DDIM;

    float2 vv = *(const float2*)&y[base + lane * 2];
    float s  = vv.x + vv.y;
    float sq = vv.x * vv.x + vv.y * vv.y;
#pragma unroll
    for (int o = 16; o > 0; o >>= 1) {
        s  += __shfl_xor_sync(0xffffffffu, s,  o);
        sq += __shfl_xor_sync(0xffffffffu, sq, o);
    }
    float mean = s * (1.f / 64.f);
    float var  = sq * (1.f / 64.f) - mean * mean;
    float inv  = rsqrtf(var + 1e-5f * (float)HNUM);

    int c0 = h * DDIM + lane * 2;
    float2 gv = *(const float2*)&g[base + lane * 2];
    float o0 = ((vv.x - mean) * inv * gamma[c0]     + beta[c0])     * gv.x;
    float o1 = ((vv.y - mean) * inv * gamma[c0 + 1] + beta[c0 + 1]) * gv.y;

    __nv_bfloat16 h0 = __float2bfloat16(o0), h1 = __float2bfloat16(o1);
    __nv_bfloat16 l0 = __float2bfloat16(o0 - __bfloat162float(h0));
    __nv_bfloat16 l1 = __float2bfloat16(o1 - __bfloat162float(h1));
    __nv_bfloat162 H = __halves2bfloat162(h0, h1), L = __halves2bfloat162(l0, l1);
    *(uint32_t*)(yhi + base + lane * 2) = *(uint32_t*)&H;
    *(uint32_t*)(ylo + base + lane * 2) = *(uint32_t*)&L;
}

// ======================================================================================
extern "C" void kernel_launch(void* const* d_in, const int* in_sizes, int n_in,
                              void* d_out, int out_size)
{
    const float* x    = (const float*)d_in[0];
    const float* xlst = (const float*)d_in[1];
    const float* s_in = (const float*)d_in[2];
    const float* miux = (const float*)d_in[3];
    const float* lam  = (const float*)d_in[4];
    const float* Aw   = (const float*)d_in[5];
    const float* Blo5 = (const float*)d_in[6];
    const float* tdm  = (const float*)d_in[7];
    const float* tdA  = (const float*)d_in[8];
    const float* tdB  = (const float*)d_in[9];
    const float* u    = (const float*)d_in[10];
    const float* Wk   = (const float*)d_in[11];
    const float* Wv   = (const float*)d_in[12];
    const float* Wr   = (const float*)d_in[13];
    const float* Wo   = (const float*)d_in[14];
    const float* Wg1  = (const float*)d_in[15];
    const float* Wg2  = (const float*)d_in[16];
    const float* gam  = (const float*)d_in[17];
    const float* bet  = (const float*)d_in[18];
    float* out = (float*)d_out;

    float *t1, *w0, *h1, *w, *dec, *kb, *vb, *rb, *gb, *yb, *cv;
    __nv_bfloat16 *xlhi, *xllo, *g0hi, *g0lo, *g1hi, *g1lo;
    __nv_bfloat16 *khi, *klo, *vhi, *vlo, *rhi, *rlo, *yhi, *ylo, *Whi, *Wlo;
    __nv_bfloat16 *Athi, *Atlo, *G1thi, *G1tlo, *G2thi, *G2tlo;
    cudaGetSymbolAddress((void**)&t1,  g_t1);
    cudaGetSymbolAddress((void**)&w0,  g_w0);
    cudaGetSymbolAddress((void**)&xlhi, g_xlhi); cudaGetSymbolAddress((void**)&xllo, g_xllo);
    cudaGetSymbolAddress((void**)&g0hi, g_g0hi); cudaGetSymbolAddress((void**)&g0lo, g_g0lo);
    cudaGetSymbolAddress((void**)&g1hi, g_g1hi); cudaGetSymbolAddress((void**)&g1lo, g_g1lo);
    cudaGetSymbolAddress((void**)&khi, g_khi); cudaGetSymbolAddress((void**)&klo, g_klo);
    cudaGetSymbolAddress((void**)&vhi, g_vhi); cudaGetSymbolAddress((void**)&vlo, g_vlo);
    cudaGetSymbolAddress((void**)&rhi, g_rhi); cudaGetSymbolAddress((void**)&rlo, g_rlo);
    cudaGetSymbolAddress((void**)&yhi, g_yhi); cudaGetSymbolAddress((void**)&ylo, g_ylo);
    cudaGetSymbolAddress((void**)&Whi, g_Whi); cudaGetSymbolAddress((void**)&Wlo, g_Wlo);
    cudaGetSymbolAddress((void**)&Athi, g_Athi); cudaGetSymbolAddress((void**)&Atlo, g_Atlo);
    cudaGetSymbolAddress((void**)&G1thi, g_G1thi); cudaGetSymbolAddress((void**)&G1tlo, g_G1tlo);
    cudaGetSymbolAddress((void**)&G2thi, g_G2thi); cudaGetSymbolAddress((void**)&G2tlo, g_G2tlo);
    cudaGetSymbolAddress((void**)&h1,  g_h1);
    cudaGetSymbolAddress((void**)&w,   g_w);
    cudaGetSymbolAddress((void**)&dec, g_dec);
    cudaGetSymbolAddress((void**)&kb,  g_kb);
    cudaGetSymbolAddress((void**)&vb,  g_vb);
    cudaGetSymbolAddress((void**)&rb,  g_rb);
    cudaGetSymbolAddress((void**)&gb,  g_gb);
    cudaGetSymbolAddress((void**)&yb,  g_yb);
    cudaGetSymbolAddress((void**)&cv,  g_cv);

    const size_t WSZ = (size_t)CDIM * CDIM;
    const size_t MC = (size_t)MROWS * CDIM;
    cudaFuncSetAttribute(mma_gemm16<0, 32>, cudaFuncAttributeMaxDynamicSharedMemorySize, 3 * STGB);
    cudaFuncSetAttribute(mma_gemm16<0, 5>,  cudaFuncAttributeMaxDynamicSharedMemorySize, 3 * STGB);
    cudaFuncSetAttribute(mma_gemm16<2, 32>, cudaFuncAttributeMaxDynamicSharedMemorySize, 3 * STGB);
    cudaFuncSetAttribute(mma_gemm16<3, 32>, cudaFuncAttributeMaxDynamicSharedMemorySize, 3 * STGB);
    cudaFuncSetAttribute(xdd_fused, cudaFuncAttributeMaxDynamicSharedMemorySize, 81920);

    dim3 thr(256);
    const int wn4 = (int)(WSZ / 4);

    // 1) xl mix -> bf16 hi/lo, x_raw passthrough
    xprep_kernel<<<(int)(MC / 4 / 256), thr>>>(
        (const float4*)x, (const float4*)xlst, miux, xlhi, xllo, (float4*)(out + MC));
    // 2) A weight transpose+pad+split (1024x160 -> 256x1024)
    tpad_split<<<(256 * CDIM + 255) / 256, thr>>>(Aw, Athi, Atlo, CDIM, 160, 256);
    // 3-5) k/v/r weight splits
    split_kernel<<<(wn4 + 255) / 256, thr>>>((const float4*)Wk, Whi + 0 * WSZ, Wlo + 0 * WSZ, wn4);
    split_kernel<<<(wn4 + 255) / 256, thr>>>((const float4*)Wv, Whi + 1 * WSZ, Wlo + 1 * WSZ, wn4);
    split_kernel<<<(wn4 + 255) / 256, thr>>>((const float4*)Wr, Whi + 2 * WSZ, Wlo + 2 * WSZ, wn4);

    // 6) t1 = tanh(xl @ A)  (HMMA, N padded 256, ncu -s 5 lands here)
    {
        GemmBatch gbat = {};
        gbat.s[0] = { xlhi, xllo, Athi, Atlo, t1, nullptr };
        mma_gemm16<2, 32><<<dim3(1, MROWS / 128, 1), thr, 3 * STGB>>>(gbat, CDIM, nullptr, nullptr);
    }

    // 7) fused xdd
    xdd_fused<<<dim3(CDIM / 64, MROWS / 64), thr, 81920>>>(
        t1, Blo5, x, xlst, lam, w0, g0hi, g0lo, khi, klo, vhi, vlo, rhi, rlo);

    // 8) h1 = tanh(w0 @ td_A)
    sgemm_bn<1><<<dim3(1, MROWS / 64), thr>>>(w0, tdA, h1, MROWS, 64, CDIM, nullptr, nullptr);
    // 9) w = tdm + h1 @ td_B ; dec = exp(-exp(w))
    sgemm_bn<4><<<dim3(CDIM / 64, MROWS / 64), thr>>>(h1, tdB, w, MROWS, CDIM, 64, tdm, dec);

    // 10) k/v/r projections, z-batched HMMA
    {
        GemmBatch gbat = {};
        gbat.s[0] = { khi, klo, Whi + 0 * WSZ, Wlo + 0 * WSZ, kb, w };
        gbat.s[1] = { vhi, vlo, Whi + 1 * WSZ, Wlo + 1 * WSZ, vb, nullptr };
        gbat.s[2] = { rhi, rlo, Whi + 2 * WSZ, Wlo + 2 * WSZ, rb, nullptr };
        mma_gemm16<0, 32><<<dim3(CDIM / 256, MROWS / 128, 3), thr, 3 * STGB>>>(gbat, CDIM, nullptr, nullptr);
    }

    // 11) remaining weight preps
    split_kernel<<<(wn4 + 255) / 256, thr>>>((const float4*)Wo, Whi + 3 * WSZ, Wlo + 3 * WSZ, wn4);
    tpad_split<<<(256 * CDIM + 255) / 256, thr>>>(Wg1, G1thi, G1tlo, CDIM, 160, 256);
    tpad_split<<<(CDIM * 160 + 255) / 256, thr>>>(Wg2, G2thi, G2tlo, 160, CDIM, CDIM);

    // 12) g1 = tanh(g0 @ W_g1) -> bf16 hi/lo
    {
        GemmBatch gbat = {};
        gbat.s[0] = { g0hi, g0lo, G1thi, G1tlo, nullptr, nullptr };
        mma_gemm16<3, 32><<<dim3(1, MROWS / 128, 1), thr, 3 * STGB>>>(gbat, CDIM, g1hi, g1lo);
    }
    // 13) g = g1 @ W_g2   (K=160)
    {
        GemmBatch gbat = {};
        gbat.s[0] = { g1hi, g1lo, G2thi, G2tlo, gb, nullptr };
        mma_gemm16<0, 5><<<dim3(CDIM / 256, MROWS / 128, 1), thr, 3 * STGB>>>(gbat, 160, nullptr, nullptr);
    }

    // 14) cvec precompute
    cvec_kernel<<<(MROWS * HNUM) / 8, thr>>>(rb, kb, u, cv);

    // 15) WKV-6 scan
    wkv_kernel<<<BSZ * HNUM, thr>>>(rb, kb, vb, dec, cv, s_in, yb, out + 2 * MC);

    // 16) GroupNorm * g -> bf16 hi/lo
    gn_kernel<<<(MROWS * HNUM) / 8, thr>>>(yb, gb, gam, bet, yhi, ylo);

    // 17) out = (yn*g) @ Wo^T
    {
        GemmBatch gbat = {};
        gbat.s[0] = { yhi, ylo, Whi + 3 * WSZ, Wlo + 3 * WSZ, out, nullptr };
        mma_gemm16<0, 32><<<dim3(CDIM / 256, MROWS / 128, 1), thr, 3 * STGB>>>(gbat, CDIM, nullptr, nullptr);
    }
}

// round 6
// speedup vs baseline: 1.9385x; 1.0323x over previous
#include <cuda_runtime.h>
#include <cuda_bf16.h>
#include <stdint.h>
#include <math.h>

#define MROWS 16384   // B*T = 8*2048
#define CDIM  1024
#define HNUM  16
#define DDIM  64
#define TSEQ  2048
#define BSZ   8

// ---------------- scratch (static device memory; no runtime allocation) ----------------
__device__ float g_t1 [(size_t)MROWS * 160];
__device__ float g_w0 [(size_t)MROWS * CDIM];
__device__ __nv_bfloat16 g_xlhi[(size_t)MROWS * CDIM], g_xllo[(size_t)MROWS * CDIM];
__device__ __nv_bfloat16 g_g0hi[(size_t)MROWS * CDIM], g_g0lo[(size_t)MROWS * CDIM];
__device__ __nv_bfloat16 g_g1hi[(size_t)MROWS * 160],  g_g1lo[(size_t)MROWS * 160];
__device__ __nv_bfloat16 g_khi[(size_t)MROWS * CDIM], g_klo[(size_t)MROWS * CDIM];
__device__ __nv_bfloat16 g_vhi[(size_t)MROWS * CDIM], g_vlo[(size_t)MROWS * CDIM];
__device__ __nv_bfloat16 g_rhi[(size_t)MROWS * CDIM], g_rlo[(size_t)MROWS * CDIM];
__device__ __nv_bfloat16 g_yhi[(size_t)MROWS * CDIM], g_ylo[(size_t)MROWS * CDIM];
__device__ __nv_bfloat16 g_Whi[4][(size_t)CDIM * CDIM], g_Wlo[4][(size_t)CDIM * CDIM];
__device__ __nv_bfloat16 g_Athi[(size_t)256 * CDIM], g_Atlo[(size_t)256 * CDIM];
__device__ __nv_bfloat16 g_G1thi[(size_t)256 * CDIM], g_G1tlo[(size_t)256 * CDIM];
__device__ __nv_bfloat16 g_G2thi[(size_t)CDIM * 160], g_G2tlo[(size_t)CDIM * 160];
__device__ float g_h1 [(size_t)MROWS * 64];
__device__ float g_w  [(size_t)MROWS * CDIM];
__device__ float g_dec[(size_t)MROWS * CDIM];
__device__ float g_kb [(size_t)MROWS * CDIM];
__device__ float g_vb [(size_t)MROWS * CDIM];
__device__ float g_rb [(size_t)MROWS * CDIM];
__device__ float g_gb [(size_t)MROWS * CDIM];
__device__ float g_yb [(size_t)MROWS * CDIM];
__device__ float g_cv [(size_t)MROWS * HNUM];

// ======================================================================================
// helpers
// ======================================================================================
__device__ __forceinline__ uint32_t smem_u32(const void* p) {
    uint32_t a;
    asm("{ .reg .u64 t; cvta.to.shared.u64 t, %1; cvt.u32.u64 %0, t; }" : "=r"(a) : "l"(p));
    return a;
}
__device__ __forceinline__ void ldsm4(uint32_t* r, uint32_t addr) {
    asm volatile("ldmatrix.sync.aligned.m8n8.x4.shared.b16 {%0,%1,%2,%3}, [%4];"
        : "=r"(r[0]), "=r"(r[1]), "=r"(r[2]), "=r"(r[3]) : "r"(addr));
}
__device__ __forceinline__ void mma16816(float* c, const uint32_t* a, const uint32_t* b) {
    asm volatile("mma.sync.aligned.m16n8k16.row.col.f32.bf16.bf16.f32 "
        "{%0,%1,%2,%3}, {%4,%5,%6,%7}, {%8,%9}, {%0,%1,%2,%3};"
        : "+f"(c[0]), "+f"(c[1]), "+f"(c[2]), "+f"(c[3])
        : "r"(a[0]), "r"(a[1]), "r"(a[2]), "r"(a[3]), "r"(b[0]), "r"(b[1]));
}
#define CP16(d, s) asm volatile("cp.async.cg.shared.global [%0], [%1], 16;" :: "r"(d), "l"(s))
#define CPCOMMIT() asm volatile("cp.async.commit_group;" ::: "memory")
#define CPWAIT1()  asm volatile("cp.async.wait_group 1;" ::: "memory")

__device__ __forceinline__ void cvt_hilo4(float4 v, uint2& hi, uint2& lo) {
    __nv_bfloat16 h0 = __float2bfloat16(v.x), h1 = __float2bfloat16(v.y);
    __nv_bfloat16 h2 = __float2bfloat16(v.z), h3 = __float2bfloat16(v.w);
    __nv_bfloat16 l0 = __float2bfloat16(v.x - __bfloat162float(h0));
    __nv_bfloat16 l1 = __float2bfloat16(v.y - __bfloat162float(h1));
    __nv_bfloat16 l2 = __float2bfloat16(v.z - __bfloat162float(h2));
    __nv_bfloat16 l3 = __float2bfloat16(v.w - __bfloat162float(h3));
    __nv_bfloat162 H01 = __halves2bfloat162(h0, h1), H23 = __halves2bfloat162(h2, h3);
    __nv_bfloat162 L01 = __halves2bfloat162(l0, l1), L23 = __halves2bfloat162(l2, l3);
    hi = make_uint2(*(uint32_t*)&H01, *(uint32_t*)&H23);
    lo = make_uint2(*(uint32_t*)&L01, *(uint32_t*)&L23);
}

// ======================================================================================
// prep kernels
// ======================================================================================
struct SplitBatch { const float* src[4]; };

__global__ void __launch_bounds__(256) split4_kernel(
    SplitBatch sb, __nv_bfloat16* __restrict__ hi,
    __nv_bfloat16* __restrict__ lo, int n4)
{
    int idx = blockIdx.x * 256 + threadIdx.x;
    if (idx >= n4) return;
    const size_t zoff = (size_t)blockIdx.y * CDIM * CDIM;
    uint2 h, l;
    cvt_hilo4(((const float4*)sb.src[blockIdx.y])[idx], h, l);
    *(uint2*)(hi + zoff + (size_t)idx * 4) = h;
    *(uint2*)(lo + zoff + (size_t)idx * 4) = l;
}

// transpose + zero-pad + split: in (K x N) -> out (Npad x K), out[n,k]=in[k,n]
__global__ void __launch_bounds__(256) tpad_split(
    const float* __restrict__ in, __nv_bfloat16* __restrict__ ohi,
    __nv_bfloat16* __restrict__ olo, int K, int N, int Npad)
{
    int t = blockIdx.x * 256 + threadIdx.x;
    if (t >= Npad * K) return;
    int n = t / K, k = t - n * K;
    float v = (n < N) ? in[(size_t)k * N + n] : 0.f;
    __nv_bfloat16 h = __float2bfloat16(v);
    __nv_bfloat16 l = __float2bfloat16(v - __bfloat162float(h));
    ohi[t] = h; olo[t] = l;
}

// xl = x + (x_last - x)*miu_x -> bf16 hi/lo ; also x_raw passthrough
__global__ void __launch_bounds__(256) xprep_kernel(
    const float4* __restrict__ x, const float4* __restrict__ xl,
    const float* __restrict__ miux,
    __nv_bfloat16* __restrict__ xhi, __nv_bfloat16* __restrict__ xlo,
    float4* __restrict__ xraw)
{
    int idx = blockIdx.x * 256 + threadIdx.x;   // MC/4 total
    float4 xv = x[idx], xlv = xl[idx];
    float4 mv = *(const float4*)(miux + (idx & 255) * 4);
    float4 o;
    o.x = fmaf(xlv.x - xv.x, mv.x, xv.x);
    o.y = fmaf(xlv.y - xv.y, mv.y, xv.y);
    o.z = fmaf(xlv.z - xv.z, mv.z, xv.z);
    o.w = fmaf(xlv.w - xv.w, mv.w, xv.w);
    uint2 h, l;
    cvt_hilo4(o, h, l);
    *(uint2*)(xhi + (size_t)idx * 4) = h;
    *(uint2*)(xlo + (size_t)idx * 4) = l;
    xraw[idx] = xv;
}

// ======================================================================================
// bf16x3 HMMA GEMM, cp.async 2-stage pipeline, 2 CTA/SM. C[m,n] = sum_k A[m,k]*B[n,k].
// Tile 128m x 128n, BK=32, KCH chunks (K = KCH*32), row stride kst.
// EPI 0: fp32 store stride CDIM, optional *exp(min(w,0)) (z-batched)
// EPI 2: tanh -> fp32 store stride 160, n<160 only
// EPI 3: tanh -> bf16 hi/lo store stride 160, n<160 only
// ======================================================================================
#define STGB2 40960
#define OAL2  10240
#define OBH2  20480
#define OBL2  30720

struct GemmSet {
    const __nv_bfloat16 *ahi, *alo, *bhi, *blo;
    float* c;
    const float* wptr;
};
struct GemmBatch { GemmSet s[3]; };

template <int EPI, int KCH>
__global__ void __launch_bounds__(256, 2) mma_gemm16(
    GemmBatch gbat, int kst,
    __nv_bfloat16* __restrict__ chi, __nv_bfloat16* __restrict__ clo)
{
    const GemmSet gs = gbat.s[blockIdx.z];
    extern __shared__ char smem[];
    const int tid = threadIdx.x, wid = tid >> 5, lane = tid & 31;
    const int bm = blockIdx.y, bn = blockIdx.x;
    const uint32_t sbase = smem_u32(smem);

    const int row = tid >> 1, half = tid & 1;     // 128 rows x 2 halves (32B each)
    const __nv_bfloat16* pAhi = gs.ahi + (size_t)(bm * 128 + row) * kst + half * 16;
    const __nv_bfloat16* pAlo = gs.alo + (size_t)(bm * 128 + row) * kst + half * 16;
    const __nv_bfloat16* pBhi = gs.bhi + (size_t)(bn * 128 + row) * kst + half * 16;
    const __nv_bfloat16* pBlo = gs.blo + (size_t)(bn * 128 + row) * kst + half * 16;
    const uint32_t dA = (uint32_t)(row * 80 + half * 32);

    auto issue = [&](int s, int k0) {
        uint32_t sb2 = sbase + s * STGB2;
        CP16(sb2 + dA,             pAhi + k0); CP16(sb2 + dA + 16,        pAhi + k0 + 8);
        CP16(sb2 + OAL2 + dA,      pAlo + k0); CP16(sb2 + OAL2 + dA + 16, pAlo + k0 + 8);
        CP16(sb2 + OBH2 + dA,      pBhi + k0); CP16(sb2 + OBH2 + dA + 16, pBhi + k0 + 8);
        CP16(sb2 + OBL2 + dA,      pBlo + k0); CP16(sb2 + OBL2 + dA + 16, pBlo + k0 + 8);
    };

    float acc[2][8][4];
#pragma unroll
    for (int a = 0; a < 2; a++)
#pragma unroll
        for (int b = 0; b < 8; b++)
#pragma unroll
            for (int c = 0; c < 4; c++) acc[a][b][c] = 0.f;

    const int arow = (wid & 3) * 32 + (lane & 7) + ((lane >> 3) & 1) * 8;
    const int acol8 = (lane >> 4) * 8;
    const int brow = (wid >> 2) * 64 + ((lane >> 4) << 3) + (lane & 7);
    const int bcol8 = ((lane >> 3) & 1) * 8;

    issue(0, 0);  CPCOMMIT();
    if (KCH > 1) issue(1, 32);
    CPCOMMIT();

    for (int c = 0; c < KCH; c++) {
        CPWAIT1();
        __syncthreads();
        const uint32_t sA = sbase + (c & 1) * STGB2;
#pragma unroll
        for (int ks = 0; ks < 2; ks++) {
            const int kc = ks * 16;
            uint32_t ah[2][4], al[2][4];
#pragma unroll
            for (int mt = 0; mt < 2; mt++) {
                uint32_t off = (uint32_t)((arow + mt * 16) * 40 + kc + acol8) * 2;
                ldsm4(ah[mt], sA + off);
                ldsm4(al[mt], sA + OAL2 + off);
            }
#pragma unroll
            for (int nt2 = 0; nt2 < 4; nt2++) {
                uint32_t boff = (uint32_t)((brow + nt2 * 16) * 40 + kc + bcol8) * 2;
                uint32_t rh[4], rl[4];
                ldsm4(rh, sA + OBH2 + boff);
                ldsm4(rl, sA + OBL2 + boff);
#pragma unroll
                for (int mt = 0; mt < 2; mt++) {
                    mma16816(acc[mt][nt2 * 2], ah[mt], rh);
                    mma16816(acc[mt][nt2 * 2], ah[mt], rl);
                    mma16816(acc[mt][nt2 * 2], al[mt], rh);
                    mma16816(acc[mt][nt2 * 2 + 1], ah[mt], rh + 2);
                    mma16816(acc[mt][nt2 * 2 + 1], ah[mt], rl + 2);
                    mma16816(acc[mt][nt2 * 2 + 1], al[mt], rh + 2);
                }
            }
        }
        __syncthreads();
        {
            int cn = c + 2;
            if (cn < KCH) issue(cn & 1, cn * 32);
            CPCOMMIT();
        }
    }

    // epilogue
#pragma unroll
    for (int mt = 0; mt < 2; mt++) {
        const int m = bm * 128 + (wid & 3) * 32 + mt * 16 + (lane >> 2);
#pragma unroll
        for (int nt = 0; nt < 8; nt++) {
            const int n = bn * 128 + (wid >> 2) * 64 + nt * 8 + (lane & 3) * 2;
            float c0 = acc[mt][nt][0], c1 = acc[mt][nt][1];
            float c2 = acc[mt][nt][2], c3 = acc[mt][nt][3];
            if (EPI == 0) {
                size_t i0 = (size_t)m * CDIM + n;
                size_t i1 = i0 + (size_t)8 * CDIM;
                if (gs.wptr) {
                    float2 wa = *(const float2*)(gs.wptr + i0);
                    float2 wb = *(const float2*)(gs.wptr + i1);
                    c0 *= __expf(fminf(wa.x, 0.f)); c1 *= __expf(fminf(wa.y, 0.f));
                    c2 *= __expf(fminf(wb.x, 0.f)); c3 *= __expf(fminf(wb.y, 0.f));
                }
                *(float2*)(gs.c + i0) = make_float2(c0, c1);
                *(float2*)(gs.c + i1) = make_float2(c2, c3);
            } else {
                if (n >= 160) continue;
                c0 = tanhf(c0); c1 = tanhf(c1); c2 = tanhf(c2); c3 = tanhf(c3);
                size_t i0 = (size_t)m * 160 + n;
                size_t i1 = i0 + (size_t)8 * 160;
                if (EPI == 2) {
                    *(float2*)(gs.c + i0) = make_float2(c0, c1);
                    *(float2*)(gs.c + i1) = make_float2(c2, c3);
                } else {
                    __nv_bfloat16 h0 = __float2bfloat16(c0), h1 = __float2bfloat16(c1);
                    __nv_bfloat16 h2 = __float2bfloat16(c2), h3 = __float2bfloat16(c3);
                    __nv_bfloat16 l0 = __float2bfloat16(c0 - __bfloat162float(h0));
                    __nv_bfloat16 l1 = __float2bfloat16(c1 - __bfloat162float(h1));
                    __nv_bfloat16 l2 = __float2bfloat16(c2 - __bfloat162float(h2));
                    __nv_bfloat16 l3 = __float2bfloat16(c3 - __bfloat162float(h3));
                    __nv_bfloat162 H01 = __halves2bfloat162(h0, h1), H23 = __halves2bfloat162(h2, h3);
                    __nv_bfloat162 L01 = __halves2bfloat162(l0, l1), L23 = __halves2bfloat162(l2, l3);
                    *(uint32_t*)(chi + i0) = *(uint32_t*)&H01;
                    *(uint32_t*)(chi + i1) = *(uint32_t*)&H23;
                    *(uint32_t*)(clo + i0) = *(uint32_t*)&L01;
                    *(uint32_t*)(clo + i1) = *(uint32_t*)&L23;
                }
            }
        }
    }
}

// ======================================================================================
// fused xdd (K=32 LoRA): w0 fp32; g0/k0/v0/r0 -> bf16 hi/lo
// ======================================================================================
__global__ void __launch_bounds__(256) xdd_fused(
    const float* __restrict__ t1, const float* __restrict__ Blo5,
    const float* __restrict__ x, const float* __restrict__ xl,
    const float* __restrict__ lam,
    float* __restrict__ w0,
    __nv_bfloat16* __restrict__ g0hi, __nv_bfloat16* __restrict__ g0lo,
    __nv_bfloat16* __restrict__ khi, __nv_bfloat16* __restrict__ klo,
    __nv_bfloat16* __restrict__ vhi, __nv_bfloat16* __restrict__ vlo,
    __nv_bfloat16* __restrict__ rhi, __nv_bfloat16* __restrict__ rlo)
{
    extern __shared__ float sh[];
    float* T1 = sh;              // [5][64][32]
    float* BL = sh + 10240;      // [5][32][64]
    const int tid = threadIdx.x;
    const int bm = blockIdx.y, bn = blockIdx.x;
    const int tx = tid & 15, ty = tid >> 4;

#pragma unroll
    for (int ii = 0; ii < 10; ii++) {
        int c4 = tid + ii * 256;
        int f = c4 >> 9, rem = c4 & 511;
        int row = rem >> 3, kq = rem & 7;
        float4 v = *(const float4*)(t1 + (size_t)f * MROWS * 32 + (size_t)(bm * 64 + row) * 32 + kq * 4);
        *(float4*)&T1[(f * 64 + row) * 32 + kq * 4] = v;
    }
#pragma unroll
    for (int ii = 0; ii < 10; ii++) {
        int c4 = tid + ii * 256;
        int f = c4 >> 9, rem = c4 & 511;
        int k = rem >> 4, cq = rem & 15;
        float4 v = *(const float4*)(Blo5 + (size_t)f * 32 * CDIM + (size_t)k * CDIM + bn * 64 + cq * 4);
        *(float4*)&BL[(f * 32 + k) * 64 + cq * 4] = v;
    }
    __syncthreads();

    float acc[5][4][4];
#pragma unroll
    for (int f = 0; f < 5; f++)
#pragma unroll
        for (int i = 0; i < 4; i++)
#pragma unroll
            for (int j = 0; j < 4; j++) acc[f][i][j] = 0.f;

    for (int k = 0; k < 32; k++) {
#pragma unroll
        for (int f = 0; f < 5; f++) {
            float4 b = *(const float4*)&BL[(f * 32 + k) * 64 + tx * 4];
            float a0 = T1[(f * 64 + ty * 4 + 0) * 32 + k];
            float a1 = T1[(f * 64 + ty * 4 + 1) * 32 + k];
            float a2 = T1[(f * 64 + ty * 4 + 2) * 32 + k];
            float a3 = T1[(f * 64 + ty * 4 + 3) * 32 + k];
            acc[f][0][0] = fmaf(a0, b.x, acc[f][0][0]); acc[f][0][1] = fmaf(a0, b.y, acc[f][0][1]);
            acc[f][0][2] = fmaf(a0, b.z, acc[f][0][2]); acc[f][0][3] = fmaf(a0, b.w, acc[f][0][3]);
            acc[f][1][0] = fmaf(a1, b.x, acc[f][1][0]); acc[f][1][1] = fmaf(a1, b.y, acc[f][1][1]);
            acc[f][1][2] = fmaf(a1, b.z, acc[f][1][2]); acc[f][1][3] = fmaf(a1, b.w, acc[f][1][3]);
            acc[f][2][0] = fmaf(a2, b.x, acc[f][2][0]); acc[f][2][1] = fmaf(a2, b.y, acc[f][2][1]);
            acc[f][2][2] = fmaf(a2, b.z, acc[f][2][2]); acc[f][2][3] = fmaf(a2, b.w, acc[f][2][3]);
            acc[f][3][0] = fmaf(a3, b.x, acc[f][3][0]); acc[f][3][1] = fmaf(a3, b.y, acc[f][3][1]);
            acc[f][3][2] = fmaf(a3, b.z, acc[f][3][2]); acc[f][3][3] = fmaf(a3, b.w, acc[f][3][3]);
        }
    }

    const int n0 = bn * 64 + tx * 4;
    float4 lamv[5];
#pragma unroll
    for (int f = 0; f < 5; f++) lamv[f] = *(const float4*)(lam + f * CDIM + n0);

#pragma unroll
    for (int i = 0; i < 4; i++) {
        const int m = bm * 64 + ty * 4 + i;
        size_t ix = (size_t)m * CDIM + n0;
        float4 xv = *(const float4*)(x + ix);
        float4 xlv = *(const float4*)(xl + ix);
        float4 ba = make_float4(xlv.x - xv.x, xlv.y - xv.y, xlv.z - xv.z, xlv.w - xv.w);
        float4 o[5];
#pragma unroll
        for (int f = 0; f < 5; f++) {
            o[f].x = fmaf(ba.x, lamv[f].x + acc[f][i][0], xv.x);
            o[f].y = fmaf(ba.y, lamv[f].y + acc[f][i][1], xv.y);
            o[f].z = fmaf(ba.z, lamv[f].z + acc[f][i][2], xv.z);
            o[f].w = fmaf(ba.w, lamv[f].w + acc[f][i][3], xv.w);
        }
        *(float4*)(w0 + ix) = o[0];
        uint2 h, l;
        cvt_hilo4(o[1], h, l); *(uint2*)(khi + ix) = h; *(uint2*)(klo + ix) = l;
        cvt_hilo4(o[2], h, l); *(uint2*)(vhi + ix) = h; *(uint2*)(vlo + ix) = l;
        cvt_hilo4(o[3], h, l); *(uint2*)(rhi + ix) = h; *(uint2*)(rlo + ix) = l;
        cvt_hilo4(o[4], h, l); *(uint2*)(g0hi + ix) = h; *(uint2*)(g0lo + ix) = l;
    }
}

// ======================================================================================
// small FFMA GEMM (B normal). EPI: 1 tanh; 4 +=p0[n] & dec=exp(-exp(c))
// ======================================================================================
template <int EPI>
__global__ void __launch_bounds__(256) sgemm_bn(
    const float* __restrict__ A, const float* __restrict__ B, float* __restrict__ C,
    int M, int N, int K, const float* __restrict__ p0, float* __restrict__ dout)
{
    __shared__ float As[16][68];
    __shared__ float Bs[16][64];
    const int tid = threadIdx.x;
    const int bm = blockIdx.y, bn = blockIdx.x;
    const int arow = tid >> 2, acol = (tid & 3) << 2;
    const int brow = tid >> 4, bcol = (tid & 15) << 2;
    const int tx = tid & 15, ty = tid >> 4;
    const int gm_a = bm * 64 + arow;
    const int gn_b = bn * 64 + bcol;

    float acc[4][4];
#pragma unroll
    for (int i = 0; i < 4; i++)
#pragma unroll
        for (int j = 0; j < 4; j++) acc[i][j] = 0.f;

    for (int k0 = 0; k0 < K; k0 += 16) {
        float4 a4 = *(const float4*)(A + (size_t)gm_a * K + k0 + acol);
        As[acol + 0][arow] = a4.x; As[acol + 1][arow] = a4.y;
        As[acol + 2][arow] = a4.z; As[acol + 3][arow] = a4.w;

        float4 b4 = make_float4(0.f, 0.f, 0.f, 0.f);
        if (gn_b < N)
            b4 = *(const float4*)(B + (size_t)(k0 + brow) * N + gn_b);
        Bs[brow][bcol + 0] = b4.x; Bs[brow][bcol + 1] = b4.y;
        Bs[brow][bcol + 2] = b4.z; Bs[brow][bcol + 3] = b4.w;
        __syncthreads();
#pragma unroll
        for (int kk = 0; kk < 16; kk++) {
            float4 a = *(const float4*)&As[kk][ty * 4];
            float4 b = *(const float4*)&Bs[kk][tx * 4];
            acc[0][0] = fmaf(a.x, b.x, acc[0][0]); acc[0][1] = fmaf(a.x, b.y, acc[0][1]);
            acc[0][2] = fmaf(a.x, b.z, acc[0][2]); acc[0][3] = fmaf(a.x, b.w, acc[0][3]);
            acc[1][0] = fmaf(a.y, b.x, acc[1][0]); acc[1][1] = fmaf(a.y, b.y, acc[1][1]);
            acc[1][2] = fmaf(a.y, b.z, acc[1][2]); acc[1][3] = fmaf(a.y, b.w, acc[1][3]);
            acc[2][0] = fmaf(a.z, b.x, acc[2][0]); acc[2][1] = fmaf(a.z, b.y, acc[2][1]);
            acc[2][2] = fmaf(a.z, b.z, acc[2][2]); acc[2][3] = fmaf(a.z, b.w, acc[2][3]);
            acc[3][0] = fmaf(a.w, b.x, acc[3][0]); acc[3][1] = fmaf(a.w, b.y, acc[3][1]);
            acc[3][2] = fmaf(a.w, b.z, acc[3][2]); acc[3][3] = fmaf(a.w, b.w, acc[3][3]);
        }
        __syncthreads();
    }

#pragma unroll
    for (int i = 0; i < 4; i++) {
        int m = bm * 64 + ty * 4 + i;
#pragma unroll
        for (int j = 0; j < 4; j++) {
            int n = bn * 64 + tx * 4 + j;
            if (n >= N) continue;
            float c = acc[i][j];
            size_t ix = (size_t)m * N + n;
            if (EPI == 1) c = tanhf(c);
            else if (EPI == 4) {
                c += p0[n];
                dout[ix] = __expf(-__expf(c));
            }
            C[ix] = c;
        }
    }
}

// ======================================================================================
// cvec[m,h] = sum_j r*u*k
// ======================================================================================
__global__ void __launch_bounds__(256) cvec_kernel(
    const float* __restrict__ rb, const float* __restrict__ kb,
    const float* __restrict__ u, float* __restrict__ cv)
{
    int gw = (blockIdx.x * 256 + threadIdx.x) >> 5;
    int lane = threadIdx.x & 31;
    int m = gw >> 4, h = gw & 15;
    size_t base = (size_t)m * CDIM + h * DDIM;
    float p = rb[base + lane] * u[h * DDIM + lane] * kb[base + lane]
            + rb[base + 32 + lane] * u[h * DDIM + 32 + lane] * kb[base + 32 + lane];
#pragma unroll
    for (int o = 16; o > 0; o >>= 1) p += __shfl_xor_sync(0xffffffffu, p, o);
    if (lane == 0) cv[(size_t)m * HNUM + h] = p;
}

// ======================================================================================
// WKV-6 scan — single __syncthreads per step
// ======================================================================================
__global__ void __launch_bounds__(256) wkv_kernel(
    const float* __restrict__ r, const float* __restrict__ k,
    const float* __restrict__ v, const float* __restrict__ dec,
    const float* __restrict__ cv, const float* __restrict__ s_in,
    float* __restrict__ y, float* __restrict__ s_out)
{
    const int bh = blockIdx.x;
    const int b = bh >> 4, h = bh & 15;
    const int tid = threadIdx.x;
    const int i  = tid & 63;
    const int jg = tid >> 6;
    const int j0 = jg * 16;

    __shared__ float buf[2][4][64];
    __shared__ float ypart[2][4][64];
    __shared__ float cb[2];

    float st[16];
    size_t sbase = (((size_t)b * HNUM + h) * DDIM + j0) * DDIM + i;
#pragma unroll
    for (int q = 0; q < 16; q++) st[q] = s_in[sbase + (size_t)q * DDIM];

    const int arr = tid >> 6, idx = tid & 63;
    const float* lp = (arr == 0) ? r : (arr == 1) ? k : (arr == 2) ? v : dec;
    const size_t base0 = ((size_t)b * TSEQ) * CDIM + h * DDIM;

    buf[0][arr][idx] = lp[base0 + idx];
    if (tid == 0) cb[0] = cv[(size_t)(b * TSEQ) * HNUM + h];
    float ld = (TSEQ > 1) ? lp[base0 + CDIM + idx] : 0.f;
    float cn = 0.f;
    if (tid == 0 && TSEQ > 1) cn = cv[(size_t)(b * TSEQ + 1) * HNUM + h];
    __syncthreads();

    for (int t = 0; t < TSEQ; t++) {
        const int cur = t & 1, nxt = cur ^ 1;

        const float vi = buf[cur][2][i];
        float acc = 0.f;
#pragma unroll
        for (int q = 0; q < 16; q += 4) {
            float4 r4 = *(const float4*)&buf[cur][0][j0 + q];
            float4 k4 = *(const float4*)&buf[cur][1][j0 + q];
            float4 d4 = *(const float4*)&buf[cur][3][j0 + q];
            acc = fmaf(r4.x, st[q + 0], acc); st[q + 0] = fmaf(d4.x, st[q + 0], k4.x * vi);
            acc = fmaf(r4.y, st[q + 1], acc); st[q + 1] = fmaf(d4.y, st[q + 1], k4.y * vi);
            acc = fmaf(r4.z, st[q + 2], acc); st[q + 2] = fmaf(d4.z, st[q + 2], k4.z * vi);
            acc = fmaf(r4.w, st[q + 3], acc); st[q + 3] = fmaf(d4.w, st[q + 3], k4.w * vi);
        }
        ypart[cur][jg][i] = acc;

        float vcur = 0.f, ccur = 0.f;
        if (tid < 64) { vcur = buf[cur][2][tid]; ccur = cb[cur]; }
        if (t + 1 < TSEQ) {
            buf[nxt][arr][idx] = ld;
            if (tid == 0) cb[nxt] = cn;
        }
        __syncthreads();

        if (t + 2 < TSEQ) {
            ld = lp[base0 + (size_t)(t + 2) * CDIM + idx];
            if (tid == 0) cn = cv[(size_t)(b * TSEQ + t + 2) * HNUM + h];
        }
        if (tid < 64) {
            float yv = ypart[cur][0][tid] + ypart[cur][1][tid] + ypart[cur][2][tid]
                     + ypart[cur][3][tid] + vcur * ccur;
            y[base0 + (size_t)t * CDIM + tid] = yv;
        }
    }

#pragma unroll
    for (int q = 0; q < 16; q++) s_out[sbase + (size_t)q * DDIM] = st[q];
}

// ======================================================================================
// GroupNorm * g -> bf16 hi/lo
// ======================================================================================
__global__ void __launch_bounds__(256) gn_kernel(
    const float* __restrict__ y, const float* __restrict__ g,
    const float* __restrict__ gamma, const float* __restrict__ beta,
    __nv_bfloat16* __restrict__ yhi, __nv_bfloat16* __restrict__ ylo)
{
    int warp = (blockIdx.x * blockDim.x + threadIdx.x) >> 5;
    int lane = threadIdx.x & 31;
    int m = warp >> 4, h = warp & 15;
    size_t base = (size_t)m * CDIM + h * DDIM;

    float2 vv = *(const float2*)&y[base + lane * 2];
    float s  = vv.x + vv.y;
    float sq = vv.x * vv.x + vv.y * vv.y;
#pragma unroll
    for (int o = 16; o > 0; o >>= 1) {
        s  += __shfl_xor_sync(0xffffffffu, s,  o);
        sq += __shfl_xor_sync(0xffffffffu, sq, o);
    }
    float mean = s * (1.f / 64.f);
    float var  = sq * (1.f / 64.f) - mean * mean;
    float inv  = rsqrtf(var + 1e-5f * (float)HNUM);

    int c0 = h * DDIM + lane * 2;
    float2 gv = *(const float2*)&g[base + lane * 2];
    float o0 = ((vv.x - mean) * inv * gamma[c0]     + beta[c0])     * gv.x;
    float o1 = ((vv.y - mean) * inv * gamma[c0 + 1] + beta[c0 + 1]) * gv.y;

    __nv_bfloat16 h0 = __float2bfloat16(o0), h1 = __float2bfloat16(o1);
    __nv_bfloat16 l0 = __float2bfloat16(o0 - __bfloat162float(h0));
    __nv_bfloat16 l1 = __float2bfloat16(o1 - __bfloat162float(h1));
    __nv_bfloat162 H = __halves2bfloat162(h0, h1), L = __halves2bfloat162(l0, l1);
    *(uint32_t*)(yhi + base + lane * 2) = *(uint32_t*)&H;
    *(uint32_t*)(ylo + base + lane * 2) = *(uint32_t*)&L;
}

// ======================================================================================
extern "C" void kernel_launch(void* const* d_in, const int* in_sizes, int n_in,
                              void* d_out, int out_size)
{
    const float* x    = (const float*)d_in[0];
    const float* xlst = (const float*)d_in[1];
    const float* s_in = (const float*)d_in[2];
    const float* miux = (const float*)d_in[3];
    const float* lam  = (const float*)d_in[4];
    const float* Aw   = (const float*)d_in[5];
    const float* Blo5 = (const float*)d_in[6];
    const float* tdm  = (const float*)d_in[7];
    const float* tdA  = (const float*)d_in[8];
    const float* tdB  = (const float*)d_in[9];
    const float* u    = (const float*)d_in[10];
    const float* Wk   = (const float*)d_in[11];
    const float* Wv   = (const float*)d_in[12];
    const float* Wr   = (const float*)d_in[13];
    const float* Wo   = (const float*)d_in[14];
    const float* Wg1  = (const float*)d_in[15];
    const float* Wg2  = (const float*)d_in[16];
    const float* gam  = (const float*)d_in[17];
    const float* bet  = (const float*)d_in[18];
    float* out = (float*)d_out;

    float *t1, *w0, *h1, *w, *dec, *kb, *vb, *rb, *gb, *yb, *cv;
    __nv_bfloat16 *xlhi, *xllo, *g0hi, *g0lo, *g1hi, *g1lo;
    __nv_bfloat16 *khi, *klo, *vhi, *vlo, *rhi, *rlo, *yhi, *ylo, *Whi, *Wlo;
    __nv_bfloat16 *Athi, *Atlo, *G1thi, *G1tlo, *G2thi, *G2tlo;
    cudaGetSymbolAddress((void**)&t1,  g_t1);
    cudaGetSymbolAddress((void**)&w0,  g_w0);
    cudaGetSymbolAddress((void**)&xlhi, g_xlhi); cudaGetSymbolAddress((void**)&xllo, g_xllo);
    cudaGetSymbolAddress((void**)&g0hi, g_g0hi); cudaGetSymbolAddress((void**)&g0lo, g_g0lo);
    cudaGetSymbolAddress((void**)&g1hi, g_g1hi); cudaGetSymbolAddress((void**)&g1lo, g_g1lo);
    cudaGetSymbolAddress((void**)&khi, g_khi); cudaGetSymbolAddress((void**)&klo, g_klo);
    cudaGetSymbolAddress((void**)&vhi, g_vhi); cudaGetSymbolAddress((void**)&vlo, g_vlo);
    cudaGetSymbolAddress((void**)&rhi, g_rhi); cudaGetSymbolAddress((void**)&rlo, g_rlo);
    cudaGetSymbolAddress((void**)&yhi, g_yhi); cudaGetSymbolAddress((void**)&ylo, g_ylo);
    cudaGetSymbolAddress((void**)&Whi, g_Whi); cudaGetSymbolAddress((void**)&Wlo, g_Wlo);
    cudaGetSymbolAddress((void**)&Athi, g_Athi); cudaGetSymbolAddress((void**)&Atlo, g_Atlo);
    cudaGetSymbolAddress((void**)&G1thi, g_G1thi); cudaGetSymbolAddress((void**)&G1tlo, g_G1tlo);
    cudaGetSymbolAddress((void**)&G2thi, g_G2thi); cudaGetSymbolAddress((void**)&G2tlo, g_G2tlo);
    cudaGetSymbolAddress((void**)&h1,  g_h1);
    cudaGetSymbolAddress((void**)&w,   g_w);
    cudaGetSymbolAddress((void**)&dec, g_dec);
    cudaGetSymbolAddress((void**)&kb,  g_kb);
    cudaGetSymbolAddress((void**)&vb,  g_vb);
    cudaGetSymbolAddress((void**)&rb,  g_rb);
    cudaGetSymbolAddress((void**)&gb,  g_gb);
    cudaGetSymbolAddress((void**)&yb,  g_yb);
    cudaGetSymbolAddress((void**)&cv,  g_cv);

    const size_t WSZ = (size_t)CDIM * CDIM;
    const size_t MC = (size_t)MROWS * CDIM;
    cudaFuncSetAttribute(mma_gemm16<0, 32>, cudaFuncAttributeMaxDynamicSharedMemorySize, 2 * STGB2);
    cudaFuncSetAttribute(mma_gemm16<0, 5>,  cudaFuncAttributeMaxDynamicSharedMemorySize, 2 * STGB2);
    cudaFuncSetAttribute(mma_gemm16<2, 32>, cudaFuncAttributeMaxDynamicSharedMemorySize, 2 * STGB2);
    cudaFuncSetAttribute(mma_gemm16<3, 32>, cudaFuncAttributeMaxDynamicSharedMemorySize, 2 * STGB2);
    cudaFuncSetAttribute(xdd_fused, cudaFuncAttributeMaxDynamicSharedMemorySize, 81920);

    dim3 thr(256);
    const int wn4 = (int)(WSZ / 4);

    // 1) xl mix -> bf16 hi/lo, x_raw passthrough
    xprep_kernel<<<(int)(MC / 4 / 256), thr>>>(
        (const float4*)x, (const float4*)xlst, miux, xlhi, xllo, (float4*)(out + MC));
    // 2) A weight transpose+pad+split (1024x160 -> 256x1024)
    tpad_split<<<(256 * CDIM + 255) / 256, thr>>>(Aw, Athi, Atlo, CDIM, 160, 256);
    // 3) all 4 square-weight splits, z-batched
    {
        SplitBatch sb = { { Wk, Wv, Wr, Wo } };
        split4_kernel<<<dim3((wn4 + 255) / 256, 4), thr>>>(sb, Whi, Wlo, wn4);
    }
    // 4) t1 = tanh(xl @ A)  (HMMA; this is launch #4 -> ncu capture target)
    {
        GemmBatch gbat = {};
        gbat.s[0] = { xlhi, xllo, Athi, Atlo, t1, nullptr };
        mma_gemm16<2, 32><<<dim3(2, MROWS / 128, 1), thr, 2 * STGB2>>>(gbat, CDIM, nullptr, nullptr);
    }

    // 5) fused xdd
    xdd_fused<<<dim3(CDIM / 64, MROWS / 64), thr, 81920>>>(
        t1, Blo5, x, xlst, lam, w0, g0hi, g0lo, khi, klo, vhi, vlo, rhi, rlo);

    // 6) h1 = tanh(w0 @ td_A)
    sgemm_bn<1><<<dim3(1, MROWS / 64), thr>>>(w0, tdA, h1, MROWS, 64, CDIM, nullptr, nullptr);
    // 7) w = tdm + h1 @ td_B ; dec = exp(-exp(w))
    sgemm_bn<4><<<dim3(CDIM / 64, MROWS / 64), thr>>>(h1, tdB, w, MROWS, CDIM, 64, tdm, dec);

    // 8) k/v/r projections, z-batched HMMA
    {
        GemmBatch gbat = {};
        gbat.s[0] = { khi, klo, Whi + 0 * WSZ, Wlo + 0 * WSZ, kb, w };
        gbat.s[1] = { vhi, vlo, Whi + 1 * WSZ, Wlo + 1 * WSZ, vb, nullptr };
        gbat.s[2] = { rhi, rlo, Whi + 2 * WSZ, Wlo + 2 * WSZ, rb, nullptr };
        mma_gemm16<0, 32><<<dim3(CDIM / 128, MROWS / 128, 3), thr, 2 * STGB2>>>(gbat, CDIM, nullptr, nullptr);
    }

    // 9-10) gate weight preps
    tpad_split<<<(256 * CDIM + 255) / 256, thr>>>(Wg1, G1thi, G1tlo, CDIM, 160, 256);
    tpad_split<<<(CDIM * 160 + 255) / 256, thr>>>(Wg2, G2thi, G2tlo, 160, CDIM, CDIM);

    // 11) g1 = tanh(g0 @ W_g1) -> bf16 hi/lo
    {
        GemmBatch gbat = {};
        gbat.s[0] = { g0hi, g0lo, G1thi, G1tlo, nullptr, nullptr };
        mma_gemm16<3, 32><<<dim3(2, MROWS / 128, 1), thr, 2 * STGB2>>>(gbat, CDIM, g1hi, g1lo);
    }
    // 12) g = g1 @ W_g2   (K=160)
    {
        GemmBatch gbat = {};
        gbat.s[0] = { g1hi, g1lo, G2thi, G2tlo, gb, nullptr };
        mma_gemm16<0, 5><<<dim3(CDIM / 128, MROWS / 128, 1), thr, 2 * STGB2>>>(gbat, 160, nullptr, nullptr);
    }

    // 13) cvec precompute
    cvec_kernel<<<(MROWS * HNUM) / 8, thr>>>(rb, kb, u, cv);

    // 14) WKV-6 scan
    wkv_kernel<<<BSZ * HNUM, thr>>>(rb, kb, vb, dec, cv, s_in, yb, out + 2 * MC);

    // 15) GroupNorm * g -> bf16 hi/lo
    gn_kernel<<<(MROWS * HNUM) / 8, thr>>>(yb, gb, gam, bet, yhi, ylo);

    // 16) out = (yn*g) @ Wo^T
    {
        GemmBatch gbat = {};
        gbat.s[0] = { yhi, ylo, Whi + 3 * WSZ, Wlo + 3 * WSZ, out, nullptr };
        mma_gemm16<0, 32><<<dim3(CDIM / 128, MROWS / 128, 1), thr, 2 * STGB2>>>(gbat, CDIM, nullptr, nullptr);
    }
}

// round 7
// speedup vs baseline: 2.2772x; 1.1747x over previous
#include <cuda_runtime.h>
#include <cuda_fp16.h>
#include <stdint.h>
#include <math.h>

#define MROWS 16384   // B*T = 8*2048
#define CDIM  1024
#define HNUM  16
#define DDIM  64
#define TSEQ  2048
#define BSZ   8

// ---------------- scratch (static device memory; no runtime allocation) ----------------
__device__ float g_t1 [(size_t)MROWS * 160];
__device__ __half g_xlhi[(size_t)MROWS * CDIM], g_xllo[(size_t)MROWS * CDIM];
__device__ __half g_w0hi[(size_t)MROWS * CDIM], g_w0lo[(size_t)MROWS * CDIM];
__device__ __half g_g0hi[(size_t)MROWS * CDIM], g_g0lo[(size_t)MROWS * CDIM];
__device__ __half g_g1hi[(size_t)MROWS * 160],  g_g1lo[(size_t)MROWS * 160];
__device__ __half g_h1hi[(size_t)MROWS * 64],   g_h1lo[(size_t)MROWS * 64];
__device__ __half g_khi[(size_t)MROWS * CDIM], g_klo[(size_t)MROWS * CDIM];
__device__ __half g_vhi[(size_t)MROWS * CDIM], g_vlo[(size_t)MROWS * CDIM];
__device__ __half g_rhi[(size_t)MROWS * CDIM], g_rlo[(size_t)MROWS * CDIM];
__device__ __half g_yhi[(size_t)MROWS * CDIM], g_ylo[(size_t)MROWS * CDIM];
__device__ __half g_Whi[4][(size_t)CDIM * CDIM];
__device__ __half g_Athi[(size_t)256 * CDIM];
__device__ __half g_tdAthi[(size_t)128 * CDIM];
__device__ __half g_tdBthi[(size_t)CDIM * 64];
__device__ __half g_G1thi[(size_t)256 * CDIM];
__device__ __half g_G2thi[(size_t)CDIM * 160];
__device__ float g_w  [(size_t)MROWS * CDIM];
__device__ float g_dec[(size_t)MROWS * CDIM];
__device__ float g_kb [(size_t)MROWS * CDIM];
__device__ float g_vb [(size_t)MROWS * CDIM];
__device__ float g_rb [(size_t)MROWS * CDIM];
__device__ float g_gb [(size_t)MROWS * CDIM];
__device__ float g_yb [(size_t)MROWS * CDIM];
__device__ float g_cv [(size_t)MROWS * HNUM];

// ======================================================================================
// helpers
// ======================================================================================
__device__ __forceinline__ uint32_t smem_u32(const void* p) {
    uint32_t a;
    asm("{ .reg .u64 t; cvta.to.shared.u64 t, %1; cvt.u32.u64 %0, t; }" : "=r"(a) : "l"(p));
    return a;
}
__device__ __forceinline__ void ldsm4(uint32_t* r, uint32_t addr) {
    asm volatile("ldmatrix.sync.aligned.m8n8.x4.shared.b16 {%0,%1,%2,%3}, [%4];"
        : "=r"(r[0]), "=r"(r[1]), "=r"(r[2]), "=r"(r[3]) : "r"(addr));
}
__device__ __forceinline__ void mma16816(float* c, const uint32_t* a, const uint32_t* b) {
    asm volatile("mma.sync.aligned.m16n8k16.row.col.f32.f16.f16.f32 "
        "{%0,%1,%2,%3}, {%4,%5,%6,%7}, {%8,%9}, {%0,%1,%2,%3};"
        : "+f"(c[0]), "+f"(c[1]), "+f"(c[2]), "+f"(c[3])
        : "r"(a[0]), "r"(a[1]), "r"(a[2]), "r"(a[3]), "r"(b[0]), "r"(b[1]));
}
#define CP16(d, s) asm volatile("cp.async.cg.shared.global [%0], [%1], 16;" :: "r"(d), "l"(s))
#define CPCOMMIT() asm volatile("cp.async.commit_group;" ::: "memory")
#define CPWAIT1()  asm volatile("cp.async.wait_group 1;" ::: "memory")

__device__ __forceinline__ void cvt_hilo4h(float4 v, uint2& hi, uint2& lo) {
    __half h0 = __float2half_rn(v.x), h1 = __float2half_rn(v.y);
    __half h2 = __float2half_rn(v.z), h3 = __float2half_rn(v.w);
    __half l0 = __float2half_rn(v.x - __half2float(h0));
    __half l1 = __float2half_rn(v.y - __half2float(h1));
    __half l2 = __float2half_rn(v.z - __half2float(h2));
    __half l3 = __float2half_rn(v.w - __half2float(h3));
    __half2 H01 = __halves2half2(h0, h1), H23 = __halves2half2(h2, h3);
    __half2 L01 = __halves2half2(l0, l1), L23 = __halves2half2(l2, l3);
    hi = make_uint2(*(uint32_t*)&H01, *(uint32_t*)&H23);
    lo = make_uint2(*(uint32_t*)&L01, *(uint32_t*)&L23);
}
__device__ __forceinline__ uint2 cvt_hi4(float4 v) {
    __half2 H01 = __halves2half2(__float2half_rn(v.x), __float2half_rn(v.y));
    __half2 H23 = __halves2half2(__float2half_rn(v.z), __float2half_rn(v.w));
    return make_uint2(*(uint32_t*)&H01, *(uint32_t*)&H23);
}

// ======================================================================================
// prep kernels
// ======================================================================================
struct SplitBatch { const float* src[4]; };

__global__ void __launch_bounds__(256) split4_kernel(
    SplitBatch sb, __half* __restrict__ hi, int n4)
{
    int idx = blockIdx.x * 256 + threadIdx.x;
    if (idx >= n4) return;
    const size_t zoff = (size_t)blockIdx.y * CDIM * CDIM;
    *(uint2*)(hi + zoff + (size_t)idx * 4) = cvt_hi4(((const float4*)sb.src[blockIdx.y])[idx]);
}

// transpose + zero-pad: in (K x N) -> out (Npad x K) fp16, out[n,k]=in[k,n]
__global__ void __launch_bounds__(256) tpad_h(
    const float* __restrict__ in, __half* __restrict__ ohi, int K, int N, int Npad)
{
    int t = blockIdx.x * 256 + threadIdx.x;
    if (t >= Npad * K) return;
    int n = t / K, k = t - n * K;
    float v = (n < N) ? in[(size_t)k * N + n] : 0.f;
    ohi[t] = __float2half_rn(v);
}

// xl = x + (x_last - x)*miu_x -> fp16 hi/lo ; also x_raw passthrough
__global__ void __launch_bounds__(256) xprep_kernel(
    const float4* __restrict__ x, const float4* __restrict__ xl,
    const float* __restrict__ miux,
    __half* __restrict__ xhi, __half* __restrict__ xlo,
    float4* __restrict__ xraw)
{
    int idx = blockIdx.x * 256 + threadIdx.x;   // MC/4 total
    float4 xv = x[idx], xlv = xl[idx];
    float4 mv = *(const float4*)(miux + (idx & 255) * 4);
    float4 o;
    o.x = fmaf(xlv.x - xv.x, mv.x, xv.x);
    o.y = fmaf(xlv.y - xv.y, mv.y, xv.y);
    o.z = fmaf(xlv.z - xv.z, mv.z, xv.z);
    o.w = fmaf(xlv.w - xv.w, mv.w, xv.w);
    uint2 h, l;
    cvt_hilo4h(o, h, l);
    *(uint2*)(xhi + (size_t)idx * 4) = h;
    *(uint2*)(xlo + (size_t)idx * 4) = l;
    xraw[idx] = xv;
}

// ======================================================================================
// fp16 2-pass HMMA GEMM:  C[m,n] = sum_k (Ahi+Alo)[m,k] * Bhi[n,k]
// (activations split exactly into 2 fp16 terms; weights single fp16)
// Tile 128m x 128n, BK=32, KCH chunks (K = KCH*32), row stride kst, cp.async 2-stage.
// EPI 0: fp32 store stride CDIM, optional *exp(min(w,0)) when wptr != null
// EPI 2: tanh -> fp32 store stride 160, n<160
// EPI 3: tanh -> fp16 hi/lo store stride 160, n<160
// EPI 5: tanh -> fp16 hi/lo store stride 64,  n<64
// EPI 4: c += wptr[n]; store fp32 c (gs.c) and exp(-exp(c)) -> (float*)chi
// ======================================================================================
#define STGB3 30720
#define OAL3  10240
#define OBH3  20480

struct GemmSet {
    const __half *ahi, *alo, *bhi;
    float* c;
    const float* wptr;
};
struct GemmBatch { GemmSet s[3]; };

template <int EPI, int KCH>
__global__ void __launch_bounds__(256, 2) mma_gemm16(
    GemmBatch gbat, int kst, __half* __restrict__ chi, __half* __restrict__ clo)
{
    const GemmSet gs = gbat.s[blockIdx.z];
    extern __shared__ char smem[];
    const int tid = threadIdx.x, wid = tid >> 5, lane = tid & 31;
    const int bm = blockIdx.y, bn = blockIdx.x;
    const uint32_t sbase = smem_u32(smem);

    const int row = tid >> 1, half = tid & 1;     // 128 rows x 2 halves (32B each)
    const __half* pAhi = gs.ahi + (size_t)(bm * 128 + row) * kst + half * 16;
    const __half* pAlo = gs.alo + (size_t)(bm * 128 + row) * kst + half * 16;
    const __half* pBhi = gs.bhi + (size_t)(bn * 128 + row) * kst + half * 16;
    const uint32_t dA = (uint32_t)(row * 80 + half * 32);

    auto issue = [&](int s, int k0) {
        uint32_t sb2 = sbase + s * STGB3;
        CP16(sb2 + dA,             pAhi + k0); CP16(sb2 + dA + 16,        pAhi + k0 + 8);
        CP16(sb2 + OAL3 + dA,      pAlo + k0); CP16(sb2 + OAL3 + dA + 16, pAlo + k0 + 8);
        CP16(sb2 + OBH3 + dA,      pBhi + k0); CP16(sb2 + OBH3 + dA + 16, pBhi + k0 + 8);
    };

    float acc[2][8][4];
#pragma unroll
    for (int a = 0; a < 2; a++)
#pragma unroll
        for (int b = 0; b < 8; b++)
#pragma unroll
            for (int c = 0; c < 4; c++) acc[a][b][c] = 0.f;

    const int arow = (wid & 3) * 32 + (lane & 7) + ((lane >> 3) & 1) * 8;
    const int acol8 = (lane >> 4) * 8;
    const int brow = (wid >> 2) * 64 + ((lane >> 4) << 3) + (lane & 7);
    const int bcol8 = ((lane >> 3) & 1) * 8;

    issue(0, 0);  CPCOMMIT();
    if (KCH > 1) issue(1, 32);
    CPCOMMIT();

    for (int c = 0; c < KCH; c++) {
        CPWAIT1();
        __syncthreads();
        const uint32_t sA = sbase + (c & 1) * STGB3;
#pragma unroll
        for (int ks = 0; ks < 2; ks++) {
            const int kc = ks * 16;
            uint32_t ah[2][4], al[2][4];
#pragma unroll
            for (int mt = 0; mt < 2; mt++) {
                uint32_t off = (uint32_t)((arow + mt * 16) * 40 + kc + acol8) * 2;
                ldsm4(ah[mt], sA + off);
                ldsm4(al[mt], sA + OAL3 + off);
            }
#pragma unroll
            for (int nt2 = 0; nt2 < 4; nt2++) {
                uint32_t boff = (uint32_t)((brow + nt2 * 16) * 40 + kc + bcol8) * 2;
                uint32_t rh[4];
                ldsm4(rh, sA + OBH3 + boff);
#pragma unroll
                for (int mt = 0; mt < 2; mt++) {
                    mma16816(acc[mt][nt2 * 2], ah[mt], rh);
                    mma16816(acc[mt][nt2 * 2], al[mt], rh);
                    mma16816(acc[mt][nt2 * 2 + 1], ah[mt], rh + 2);
                    mma16816(acc[mt][nt2 * 2 + 1], al[mt], rh + 2);
                }
            }
        }
        __syncthreads();
        {
            int cn = c + 2;
            if (cn < KCH) issue(cn & 1, cn * 32);
            CPCOMMIT();
        }
    }

    // epilogue
#pragma unroll
    for (int mt = 0; mt < 2; mt++) {
        const int m = bm * 128 + (wid & 3) * 32 + mt * 16 + (lane >> 2);
#pragma unroll
        for (int nt = 0; nt < 8; nt++) {
            const int n = bn * 128 + (wid >> 2) * 64 + nt * 8 + (lane & 3) * 2;
            float c0 = acc[mt][nt][0], c1 = acc[mt][nt][1];
            float c2 = acc[mt][nt][2], c3 = acc[mt][nt][3];
            if (EPI == 0) {
                size_t i0 = (size_t)m * CDIM + n;
                size_t i1 = i0 + (size_t)8 * CDIM;
                if (gs.wptr) {
                    float2 wa = *(const float2*)(gs.wptr + i0);
                    float2 wb = *(const float2*)(gs.wptr + i1);
                    c0 *= __expf(fminf(wa.x, 0.f)); c1 *= __expf(fminf(wa.y, 0.f));
                    c2 *= __expf(fminf(wb.x, 0.f)); c3 *= __expf(fminf(wb.y, 0.f));
                }
                *(float2*)(gs.c + i0) = make_float2(c0, c1);
                *(float2*)(gs.c + i1) = make_float2(c2, c3);
            } else if (EPI == 4) {
                size_t i0 = (size_t)m * CDIM + n;
                size_t i1 = i0 + (size_t)8 * CDIM;
                c0 += gs.wptr[n];     c1 += gs.wptr[n + 1];
                c2 += gs.wptr[n];     c3 += gs.wptr[n + 1];
                float* dec = (float*)chi;
                *(float2*)(gs.c + i0) = make_float2(c0, c1);
                *(float2*)(gs.c + i1) = make_float2(c2, c3);
                *(float2*)(dec + i0) = make_float2(__expf(-__expf(c0)), __expf(-__expf(c1)));
                *(float2*)(dec + i1) = make_float2(__expf(-__expf(c2)), __expf(-__expf(c3)));
            } else {
                const int NS = (EPI == 5) ? 64 : 160;
                if (n >= NS) continue;
                c0 = tanhf(c0); c1 = tanhf(c1); c2 = tanhf(c2); c3 = tanhf(c3);
                size_t i0 = (size_t)m * NS + n;
                size_t i1 = i0 + (size_t)8 * NS;
                if (EPI == 2) {
                    *(float2*)(gs.c + i0) = make_float2(c0, c1);
                    *(float2*)(gs.c + i1) = make_float2(c2, c3);
                } else {
                    __half h0 = __float2half_rn(c0), h1 = __float2half_rn(c1);
                    __half h2 = __float2half_rn(c2), h3 = __float2half_rn(c3);
                    __half l0 = __float2half_rn(c0 - __half2float(h0));
                    __half l1 = __float2half_rn(c1 - __half2float(h1));
                    __half l2 = __float2half_rn(c2 - __half2float(h2));
                    __half l3 = __float2half_rn(c3 - __half2float(h3));
                    __half2 H01 = __halves2half2(h0, h1), H23 = __halves2half2(h2, h3);
                    __half2 L01 = __halves2half2(l0, l1), L23 = __halves2half2(l2, l3);
                    *(uint32_t*)(chi + i0) = *(uint32_t*)&H01;
                    *(uint32_t*)(chi + i1) = *(uint32_t*)&H23;
                    *(uint32_t*)(clo + i0) = *(uint32_t*)&L01;
                    *(uint32_t*)(clo + i1) = *(uint32_t*)&L23;
                }
            }
        }
    }
}

// ======================================================================================
// fused xdd (K=32 LoRA): all 5 outputs -> fp16 hi/lo
// ======================================================================================
__global__ void __launch_bounds__(256) xdd_fused(
    const float* __restrict__ t1, const float* __restrict__ Blo5,
    const float* __restrict__ x, const float* __restrict__ xl,
    const float* __restrict__ lam,
    __half* __restrict__ w0hi, __half* __restrict__ w0lo,
    __half* __restrict__ g0hi, __half* __restrict__ g0lo,
    __half* __restrict__ khi, __half* __restrict__ klo,
    __half* __restrict__ vhi, __half* __restrict__ vlo,
    __half* __restrict__ rhi, __half* __restrict__ rlo)
{
    extern __shared__ float sh[];
    float* T1 = sh;              // [5][64][32]
    float* BL = sh + 10240;      // [5][32][64]
    const int tid = threadIdx.x;
    const int bm = blockIdx.y, bn = blockIdx.x;
    const int tx = tid & 15, ty = tid >> 4;

#pragma unroll
    for (int ii = 0; ii < 10; ii++) {
        int c4 = tid + ii * 256;
        int f = c4 >> 9, rem = c4 & 511;
        int row = rem >> 3, kq = rem & 7;
        float4 v = *(const float4*)(t1 + (size_t)f * MROWS * 32 + (size_t)(bm * 64 + row) * 32 + kq * 4);
        *(float4*)&T1[(f * 64 + row) * 32 + kq * 4] = v;
    }
#pragma unroll
    for (int ii = 0; ii < 10; ii++) {
        int c4 = tid + ii * 256;
        int f = c4 >> 9, rem = c4 & 511;
        int k = rem >> 4, cq = rem & 15;
        float4 v = *(const float4*)(Blo5 + (size_t)f * 32 * CDIM + (size_t)k * CDIM + bn * 64 + cq * 4);
        *(float4*)&BL[(f * 32 + k) * 64 + cq * 4] = v;
    }
    __syncthreads();

    float acc[5][4][4];
#pragma unroll
    for (int f = 0; f < 5; f++)
#pragma unroll
        for (int i = 0; i < 4; i++)
#pragma unroll
            for (int j = 0; j < 4; j++) acc[f][i][j] = 0.f;

    for (int k = 0; k < 32; k++) {
#pragma unroll
        for (int f = 0; f < 5; f++) {
            float4 b = *(const float4*)&BL[(f * 32 + k) * 64 + tx * 4];
            float a0 = T1[(f * 64 + ty * 4 + 0) * 32 + k];
            float a1 = T1[(f * 64 + ty * 4 + 1) * 32 + k];
            float a2 = T1[(f * 64 + ty * 4 + 2) * 32 + k];
            float a3 = T1[(f * 64 + ty * 4 + 3) * 32 + k];
            acc[f][0][0] = fmaf(a0, b.x, acc[f][0][0]); acc[f][0][1] = fmaf(a0, b.y, acc[f][0][1]);
            acc[f][0][2] = fmaf(a0, b.z, acc[f][0][2]); acc[f][0][3] = fmaf(a0, b.w, acc[f][0][3]);
            acc[f][1][0] = fmaf(a1, b.x, acc[f][1][0]); acc[f][1][1] = fmaf(a1, b.y, acc[f][1][1]);
            acc[f][1][2] = fmaf(a1, b.z, acc[f][1][2]); acc[f][1][3] = fmaf(a1, b.w, acc[f][1][3]);
            acc[f][2][0] = fmaf(a2, b.x, acc[f][2][0]); acc[f][2][1] = fmaf(a2, b.y, acc[f][2][1]);
            acc[f][2][2] = fmaf(a2, b.z, acc[f][2][2]); acc[f][2][3] = fmaf(a2, b.w, acc[f][2][3]);
            acc[f][3][0] = fmaf(a3, b.x, acc[f][3][0]); acc[f][3][1] = fmaf(a3, b.y, acc[f][3][1]);
            acc[f][3][2] = fmaf(a3, b.z, acc[f][3][2]); acc[f][3][3] = fmaf(a3, b.w, acc[f][3][3]);
        }
    }

    const int n0 = bn * 64 + tx * 4;
    float4 lamv[5];
#pragma unroll
    for (int f = 0; f < 5; f++) lamv[f] = *(const float4*)(lam + f * CDIM + n0);

#pragma unroll
    for (int i = 0; i < 4; i++) {
        const int m = bm * 64 + ty * 4 + i;
        size_t ix = (size_t)m * CDIM + n0;
        float4 xv = *(const float4*)(x + ix);
        float4 xlv = *(const float4*)(xl + ix);
        float4 ba = make_float4(xlv.x - xv.x, xlv.y - xv.y, xlv.z - xv.z, xlv.w - xv.w);
        float4 o[5];
#pragma unroll
        for (int f = 0; f < 5; f++) {
            o[f].x = fmaf(ba.x, lamv[f].x + acc[f][i][0], xv.x);
            o[f].y = fmaf(ba.y, lamv[f].y + acc[f][i][1], xv.y);
            o[f].z = fmaf(ba.z, lamv[f].z + acc[f][i][2], xv.z);
            o[f].w = fmaf(ba.w, lamv[f].w + acc[f][i][3], xv.w);
        }
        uint2 h, l;
        cvt_hilo4h(o[0], h, l); *(uint2*)(w0hi + ix) = h; *(uint2*)(w0lo + ix) = l;
        cvt_hilo4h(o[1], h, l); *(uint2*)(khi + ix) = h; *(uint2*)(klo + ix) = l;
        cvt_hilo4h(o[2], h, l); *(uint2*)(vhi + ix) = h; *(uint2*)(vlo + ix) = l;
        cvt_hilo4h(o[3], h, l); *(uint2*)(rhi + ix) = h; *(uint2*)(rlo + ix) = l;
        cvt_hilo4h(o[4], h, l); *(uint2*)(g0hi + ix) = h; *(uint2*)(g0lo + ix) = l;
    }
}

// ======================================================================================
// cvec[m,h] = sum_j r*u*k
// ======================================================================================
__global__ void __launch_bounds__(256) cvec_kernel(
    const float* __restrict__ rb, const float* __restrict__ kb,
    const float* __restrict__ u, float* __restrict__ cv)
{
    int gw = (blockIdx.x * 256 + threadIdx.x) >> 5;
    int lane = threadIdx.x & 31;
    int m = gw >> 4, h = gw & 15;
    size_t base = (size_t)m * CDIM + h * DDIM;
    float p = rb[base + lane] * u[h * DDIM + lane] * kb[base + lane]
            + rb[base + 32 + lane] * u[h * DDIM + 32 + lane] * kb[base + 32 + lane];
#pragma unroll
    for (int o = 16; o > 0; o >>= 1) p += __shfl_xor_sync(0xffffffffu, p, o);
    if (lane == 0) cv[(size_t)m * HNUM + h] = p;
}

// ======================================================================================
// WKV-6 scan — single __syncthreads per step
// ======================================================================================
__global__ void __launch_bounds__(256) wkv_kernel(
    const float* __restrict__ r, const float* __restrict__ k,
    const float* __restrict__ v, const float* __restrict__ dec,
    const float* __restrict__ cv, const float* __restrict__ s_in,
    float* __restrict__ y, float* __restrict__ s_out)
{
    const int bh = blockIdx.x;
    const int b = bh >> 4, h = bh & 15;
    const int tid = threadIdx.x;
    const int i  = tid & 63;
    const int jg = tid >> 6;
    const int j0 = jg * 16;

    __shared__ float buf[2][4][64];
    __shared__ float ypart[2][4][64];
    __shared__ float cb[2];

    float st[16];
    size_t sbase = (((size_t)b * HNUM + h) * DDIM + j0) * DDIM + i;
#pragma unroll
    for (int q = 0; q < 16; q++) st[q] = s_in[sbase + (size_t)q * DDIM];

    const int arr = tid >> 6, idx = tid & 63;
    const float* lp = (arr == 0) ? r : (arr == 1) ? k : (arr == 2) ? v : dec;
    const size_t base0 = ((size_t)b * TSEQ) * CDIM + h * DDIM;

    buf[0][arr][idx] = lp[base0 + idx];
    if (tid == 0) cb[0] = cv[(size_t)(b * TSEQ) * HNUM + h];
    float ld = (TSEQ > 1) ? lp[base0 + CDIM + idx] : 0.f;
    float cn = 0.f;
    if (tid == 0 && TSEQ > 1) cn = cv[(size_t)(b * TSEQ + 1) * HNUM + h];
    __syncthreads();

    for (int t = 0; t < TSEQ; t++) {
        const int cur = t & 1, nxt = cur ^ 1;

        const float vi = buf[cur][2][i];
        float acc = 0.f;
#pragma unroll
        for (int q = 0; q < 16; q += 4) {
            float4 r4 = *(const float4*)&buf[cur][0][j0 + q];
            float4 k4 = *(const float4*)&buf[cur][1][j0 + q];
            float4 d4 = *(const float4*)&buf[cur][3][j0 + q];
            acc = fmaf(r4.x, st[q + 0], acc); st[q + 0] = fmaf(d4.x, st[q + 0], k4.x * vi);
            acc = fmaf(r4.y, st[q + 1], acc); st[q + 1] = fmaf(d4.y, st[q + 1], k4.y * vi);
            acc = fmaf(r4.z, st[q + 2], acc); st[q + 2] = fmaf(d4.z, st[q + 2], k4.z * vi);
            acc = fmaf(r4.w, st[q + 3], acc); st[q + 3] = fmaf(d4.w, st[q + 3], k4.w * vi);
        }
        ypart[cur][jg][i] = acc;

        float vcur = 0.f, ccur = 0.f;
        if (tid < 64) { vcur = buf[cur][2][tid]; ccur = cb[cur]; }
        if (t + 1 < TSEQ) {
            buf[nxt][arr][idx] = ld;
            if (tid == 0) cb[nxt] = cn;
        }
        __syncthreads();

        if (t + 2 < TSEQ) {
            ld = lp[base0 + (size_t)(t + 2) * CDIM + idx];
            if (tid == 0) cn = cv[(size_t)(b * TSEQ + t + 2) * HNUM + h];
        }
        if (tid < 64) {
            float yv = ypart[cur][0][tid] + ypart[cur][1][tid] + ypart[cur][2][tid]
                     + ypart[cur][3][tid] + vcur * ccur;
            y[base0 + (size_t)t * CDIM + tid] = yv;
        }
    }

#pragma unroll
    for (int q = 0; q < 16; q++) s_out[sbase + (size_t)q * DDIM] = st[q];
}

// ======================================================================================
// GroupNorm * g -> fp16 hi/lo
// ======================================================================================
__global__ void __launch_bounds__(256) gn_kernel(
    const float* __restrict__ y, const float* __restrict__ g,
    const float* __restrict__ gamma, const float* __restrict__ beta,
    __half* __restrict__ yhi, __half* __restrict__ ylo)
{
    int warp = (blockIdx.x * blockDim.x + threadIdx.x) >> 5;
    int lane = threadIdx.x & 31;
    int m = warp >> 4, h = warp & 15;
    size_t base = (size_t)m * CDIM + h * DDIM;

    float2 vv = *(const float2*)&y[base + lane * 2];
    float s  = vv.x + vv.y;
    float sq = vv.x * vv.x + vv.y * vv.y;
#pragma unroll
    for (int o = 16; o > 0; o >>= 1) {
        s  += __shfl_xor_sync(0xffffffffu, s,  o);
        sq += __shfl_xor_sync(0xffffffffu, sq, o);
    }
    float mean = s * (1.f / 64.f);
    float var  = sq * (1.f / 64.f) - mean * mean;
    float inv  = rsqrtf(var + 1e-5f * (float)HNUM);

    int c0 = h * DDIM + lane * 2;
    float2 gv = *(const float2*)&g[base + lane * 2];
    float o0 = ((vv.x - mean) * inv * gamma[c0]     + beta[c0])     * gv.x;
    float o1 = ((vv.y - mean) * inv * gamma[c0 + 1] + beta[c0 + 1]) * gv.y;

    __half h0 = __float2half_rn(o0), h1 = __float2half_rn(o1);
    __half l0 = __float2half_rn(o0 - __half2float(h0));
    __half l1 = __float2half_rn(o1 - __half2float(h1));
    __half2 H = __halves2half2(h0, h1), L = __halves2half2(l0, l1);
    *(uint32_t*)(yhi + base + lane * 2) = *(uint32_t*)&H;
    *(uint32_t*)(ylo + base + lane * 2) = *(uint32_t*)&L;
}

// ======================================================================================
extern "C" void kernel_launch(void* const* d_in, const int* in_sizes, int n_in,
                              void* d_out, int out_size)
{
    const float* x    = (const float*)d_in[0];
    const float* xlst = (const float*)d_in[1];
    const float* s_in = (const float*)d_in[2];
    const float* miux = (const float*)d_in[3];
    const float* lam  = (const float*)d_in[4];
    const float* Aw   = (const float*)d_in[5];
    const float* Blo5 = (const float*)d_in[6];
    const float* tdm  = (const float*)d_in[7];
    const float* tdA  = (const float*)d_in[8];
    const float* tdB  = (const float*)d_in[9];
    const float* u    = (const float*)d_in[10];
    const float* Wk   = (const float*)d_in[11];
    const float* Wv   = (const float*)d_in[12];
    const float* Wr   = (const float*)d_in[13];
    const float* Wo   = (const float*)d_in[14];
    const float* Wg1  = (const float*)d_in[15];
    const float* Wg2  = (const float*)d_in[16];
    const float* gam  = (const float*)d_in[17];
    const float* bet  = (const float*)d_in[18];
    float* out = (float*)d_out;

    float *t1, *w, *dec, *kb, *vb, *rb, *gb, *yb, *cv;
    __half *xlhi, *xllo, *w0hi, *w0lo, *g0hi, *g0lo, *g1hi, *g1lo, *h1hi, *h1lo;
    __half *khi, *klo, *vhi, *vlo, *rhi, *rlo, *yhi, *ylo, *Whi;
    __half *Athi, *tdAthi, *tdBthi, *G1thi, *G2thi;
    cudaGetSymbolAddress((void**)&t1,  g_t1);
    cudaGetSymbolAddress((void**)&xlhi, g_xlhi); cudaGetSymbolAddress((void**)&xllo, g_xllo);
    cudaGetSymbolAddress((void**)&w0hi, g_w0hi); cudaGetSymbolAddress((void**)&w0lo, g_w0lo);
    cudaGetSymbolAddress((void**)&g0hi, g_g0hi); cudaGetSymbolAddress((void**)&g0lo, g_g0lo);
    cudaGetSymbolAddress((void**)&g1hi, g_g1hi); cudaGetSymbolAddress((void**)&g1lo, g_g1lo);
    cudaGetSymbolAddress((void**)&h1hi, g_h1hi); cudaGetSymbolAddress((void**)&h1lo, g_h1lo);
    cudaGetSymbolAddress((void**)&khi, g_khi); cudaGetSymbolAddress((void**)&klo, g_klo);
    cudaGetSymbolAddress((void**)&vhi, g_vhi); cudaGetSymbolAddress((void**)&vlo, g_vlo);
    cudaGetSymbolAddress((void**)&rhi, g_rhi); cudaGetSymbolAddress((void**)&rlo, g_rlo);
    cudaGetSymbolAddress((void**)&yhi, g_yhi); cudaGetSymbolAddress((void**)&ylo, g_ylo);
    cudaGetSymbolAddress((void**)&Whi, g_Whi);
    cudaGetSymbolAddress((void**)&Athi, g_Athi);
    cudaGetSymbolAddress((void**)&tdAthi, g_tdAthi);
    cudaGetSymbolAddress((void**)&tdBthi, g_tdBthi);
    cudaGetSymbolAddress((void**)&G1thi, g_G1thi);
    cudaGetSymbolAddress((void**)&G2thi, g_G2thi);
    cudaGetSymbolAddress((void**)&w,   g_w);
    cudaGetSymbolAddress((void**)&dec, g_dec);
    cudaGetSymbolAddress((void**)&kb,  g_kb);
    cudaGetSymbolAddress((void**)&vb,  g_vb);
    cudaGetSymbolAddress((void**)&rb,  g_rb);
    cudaGetSymbolAddress((void**)&gb,  g_gb);
    cudaGetSymbolAddress((void**)&yb,  g_yb);
    cudaGetSymbolAddress((void**)&cv,  g_cv);

    const size_t WSZ = (size_t)CDIM * CDIM;
    const size_t MC = (size_t)MROWS * CDIM;
    cudaFuncSetAttribute(mma_gemm16<0, 32>, cudaFuncAttributeMaxDynamicSharedMemorySize, 2 * STGB3);
    cudaFuncSetAttribute(mma_gemm16<0, 5>,  cudaFuncAttributeMaxDynamicSharedMemorySize, 2 * STGB3);
    cudaFuncSetAttribute(mma_gemm16<2, 32>, cudaFuncAttributeMaxDynamicSharedMemorySize, 2 * STGB3);
    cudaFuncSetAttribute(mma_gemm16<3, 32>, cudaFuncAttributeMaxDynamicSharedMemorySize, 2 * STGB3);
    cudaFuncSetAttribute(mma_gemm16<5, 32>, cudaFuncAttributeMaxDynamicSharedMemorySize, 2 * STGB3);
    cudaFuncSetAttribute(mma_gemm16<4, 2>,  cudaFuncAttributeMaxDynamicSharedMemorySize, 2 * STGB3);
    cudaFuncSetAttribute(xdd_fused, cudaFuncAttributeMaxDynamicSharedMemorySize, 81920);

    dim3 thr(256);
    const int wn4 = (int)(WSZ / 4);

    // 1) xl mix -> fp16 hi/lo, x_raw passthrough
    xprep_kernel<<<(int)(MC / 4 / 256), thr>>>(
        (const float4*)x, (const float4*)xlst, miux, xlhi, xllo, (float4*)(out + MC));
    // 2) A weight transpose+pad (1024x160 -> 256x1024) fp16
    tpad_h<<<(256 * CDIM + 255) / 256, thr>>>(Aw, Athi, CDIM, 160, 256);
    // 3) all 4 square-weight fp16 casts, z-batched
    {
        SplitBatch sb = { { Wk, Wv, Wr, Wo } };
        split4_kernel<<<dim3((wn4 + 255) / 256, 4), thr>>>(sb, Whi, wn4);
    }
    // 4) t1 = tanh(xl @ A)   (launch #4 -> ncu capture target)
    {
        GemmBatch gbat = {};
        gbat.s[0] = { xlhi, xllo, Athi, t1, nullptr };
        mma_gemm16<2, 32><<<dim3(2, MROWS / 128, 1), thr, 2 * STGB3>>>(gbat, CDIM, nullptr, nullptr);
    }

    // 5-6) decay-LoRA weight preps
    tpad_h<<<(128 * CDIM + 255) / 256, thr>>>(tdA, tdAthi, CDIM, 64, 128);
    tpad_h<<<(CDIM * 64 + 255) / 256, thr>>>(tdB, tdBthi, 64, CDIM, CDIM);

    // 7) fused xdd -> all 5 branches fp16 hi/lo
    xdd_fused<<<dim3(CDIM / 64, MROWS / 64), thr, 81920>>>(
        t1, Blo5, x, xlst, lam, w0hi, w0lo, g0hi, g0lo, khi, klo, vhi, vlo, rhi, rlo);

    // 8) h1 = tanh(w0 @ td_A) -> fp16 hi/lo (stride 64)
    {
        GemmBatch gbat = {};
        gbat.s[0] = { w0hi, w0lo, tdAthi, nullptr, nullptr };
        mma_gemm16<5, 32><<<dim3(1, MROWS / 128, 1), thr, 2 * STGB3>>>(gbat, CDIM, h1hi, h1lo);
    }
    // 9) w = tdm + h1 @ td_B ; dec = exp(-exp(w))   (K=64)
    {
        GemmBatch gbat = {};
        gbat.s[0] = { h1hi, h1lo, tdBthi, w, tdm };
        mma_gemm16<4, 2><<<dim3(CDIM / 128, MROWS / 128, 1), thr, 2 * STGB3>>>(gbat, 64, (__half*)dec, nullptr);
    }

    // 10) k/v/r projections, z-batched
    {
        GemmBatch gbat = {};
        gbat.s[0] = { khi, klo, Whi + 0 * WSZ, kb, w };
        gbat.s[1] = { vhi, vlo, Whi + 1 * WSZ, vb, nullptr };
        gbat.s[2] = { rhi, rlo, Whi + 2 * WSZ, rb, nullptr };
        mma_gemm16<0, 32><<<dim3(CDIM / 128, MROWS / 128, 3), thr, 2 * STGB3>>>(gbat, CDIM, nullptr, nullptr);
    }

    // 11-12) gate weight preps
    tpad_h<<<(256 * CDIM + 255) / 256, thr>>>(Wg1, G1thi, CDIM, 160, 256);
    tpad_h<<<(CDIM * 160 + 255) / 256, thr>>>(Wg2, G2thi, 160, CDIM, CDIM);

    // 13) g1 = tanh(g0 @ W_g1) -> fp16 hi/lo
    {
        GemmBatch gbat = {};
        gbat.s[0] = { g0hi, g0lo, G1thi, nullptr, nullptr };
        mma_gemm16<3, 32><<<dim3(2, MROWS / 128, 1), thr, 2 * STGB3>>>(gbat, CDIM, g1hi, g1lo);
    }
    // 14) g = g1 @ W_g2   (K=160)
    {
        GemmBatch gbat = {};
        gbat.s[0] = { g1hi, g1lo, G2thi, gb, nullptr };
        mma_gemm16<0, 5><<<dim3(CDIM / 128, MROWS / 128, 1), thr, 2 * STGB3>>>(gbat, 160, nullptr, nullptr);
    }

    // 15) cvec precompute
    cvec_kernel<<<(MROWS * HNUM) / 8, thr>>>(rb, kb, u, cv);

    // 16) WKV-6 scan
    wkv_kernel<<<BSZ * HNUM, thr>>>(rb, kb, vb, dec, cv, s_in, yb, out + 2 * MC);

    // 17) GroupNorm * g -> fp16 hi/lo
    gn_kernel<<<(MROWS * HNUM) / 8, thr>>>(yb, gb, gam, bet, yhi, ylo);

    // 18) out = (yn*g) @ Wo^T
    {
        GemmBatch gbat = {};
        gbat.s[0] = { yhi, ylo, Whi + 3 * WSZ, out, nullptr };
        mma_gemm16<0, 32><<<dim3(CDIM / 128, MROWS / 128, 1), thr, 2 * STGB3>>>(gbat, CDIM, nullptr, nullptr);
    }
}